// round 9
// baseline (speedup 1.0000x reference)
#include <cuda_runtime.h>

// Problem constants
#define TBm 32       // T*B
#define Cc  256
#define Nn  196
#define Hh  16
#define Dd  16
#define HDd 1024
#define Jj  (TBm*Nn)     // 6272
#define EPSV 1e-5f

// ---------------- scratch (static device globals; no runtime alloc) -------------
__device__ float g_z [TBm*HDd*Nn];   // GEMM output scratch (max 1024 channels)
__device__ float g_h [TBm*HDd*Nn];   // h spikes (m1 output)
__device__ float g_s [TBm*Cc*Nn];    // attention o spikes (float 0/1)
__device__ float g_x1[TBm*Cc*Nn];
__device__ float g_y1[TBm*Cc*Nn];
__device__ float g_cur[TBm*Cc*Nn];
__device__ unsigned int g_qm[TBm*Hh*Nn];
__device__ unsigned int g_km[TBm*Hh*Nn];
__device__ unsigned int g_vm[TBm*Hh*Nn];
__device__ float g_mu[HDd];
__device__ float g_rs[HDd];

// ---------------- GEMM: out[m,d,n] = sum_c W[d,c]*A[m,c,n] ----------------
// Exact fp32, strictly ascending-k single-accumulator FMA per output element
// (bit-identical to the R6 passing kernel). Tile 64(d) x 64(j), BK=16,
// 256 threads, 4x4 per thread, DOUBLE-BUFFERED smem (1 sync/stage).
// NPASS=2: second pair (A2,W2), separate accumulators (pass0 fully, then pass1).
// MODE=0: store raw (+bias [+bias2]); MODE=1: store (v>=1)?1:0 (fused cur LIF).
template <int NPASS, int MODE>
__global__ __launch_bounds__(256) void gemm_k(
    const float* __restrict__ A, const float* __restrict__ W,
    const float* __restrict__ bias, const float* __restrict__ bias2,
    float* __restrict__ out, int Cin, int Cout,
    const float* __restrict__ A2, const float* __restrict__ W2)
{
    __shared__ float As[2][16][68];
    __shared__ float Bs[2][16][68];
    const int t  = threadIdx.x;
    const int d0 = blockIdx.y * 64;
    const int j0 = blockIdx.x * 64;
    const int tx = t & 15;
    const int ty = t >> 4;
    // B-tile load mapping: column jj fixed per thread
    const int jj = t & 63;
    const int kr = t >> 6;            // 0..3
    const int jB = j0 + jj;
    const int mB = jB / Nn;
    const int nB = jB - mB * Nn;
    // A-tile (weights) load mapping
    const int kc = t & 15;
    const int ir = t >> 4;            // 0..15

    float acc[NPASS][4][4];
#pragma unroll
    for (int p = 0; p < NPASS; p++)
#pragma unroll
        for (int i = 0; i < 4; i++)
#pragma unroll
            for (int q = 0; q < 4; q++) acc[p][i][q] = 0.f;

    float ra[4], rb[4];

#pragma unroll 1
    for (int pass = 0; pass < NPASS; ++pass) {
        const float* Ain = pass ? A2 : A;
        const float* Win = pass ? W2 : W;
        const float* aptr = Ain + (size_t)mB * Cin * Nn + nB;
        const int nst = Cin >> 4;

        // ---- pipeline prologue: stage 0 -> smem buf 0 ----
#pragma unroll
        for (int r = 0; r < 4; ++r)
            ra[r] = Win[(size_t)(d0 + ir + 16*r) * Cin + kc];
#pragma unroll
        for (int r = 0; r < 4; ++r)
            rb[r] = aptr[(size_t)(kr + 4*r) * Nn];
#pragma unroll
        for (int r = 0; r < 4; ++r) As[0][kc][ir + 16*r] = ra[r];
#pragma unroll
        for (int r = 0; r < 4; ++r) Bs[0][kr + 4*r][jj] = rb[r];
        __syncthreads();

#pragma unroll 1
        for (int s = 0; s < nst; ++s) {
            const int buf = s & 1;
            const bool more = (s + 1 < nst);
            if (more) {
                const int c0 = (s + 1) << 4;
#pragma unroll
                for (int r = 0; r < 4; ++r)
                    ra[r] = Win[(size_t)(d0 + ir + 16*r) * Cin + c0 + kc];
#pragma unroll
                for (int r = 0; r < 4; ++r)
                    rb[r] = aptr[(size_t)(c0 + kr + 4*r) * Nn];
            }
            // ---- compute stage s (ascending k; single accumulator) ----
#pragma unroll
            for (int k = 0; k < 16; ++k) {
                float4 a4 = *reinterpret_cast<const float4*>(&As[buf][k][ty * 4]);
                float a[4] = {a4.x, a4.y, a4.z, a4.w};
                float b[4];
#pragma unroll
                for (int q = 0; q < 4; q++) b[q] = Bs[buf][k][tx + 16*q];
#pragma unroll
                for (int i = 0; i < 4; i++)
#pragma unroll
                    for (int q = 0; q < 4; q++)
                        acc[pass][i][q] = __fmaf_rn(a[i], b[q], acc[pass][i][q]);
            }
            if (more) {
                const int nb = buf ^ 1;
#pragma unroll
                for (int r = 0; r < 4; ++r) As[nb][kc][ir + 16*r] = ra[r];
#pragma unroll
                for (int r = 0; r < 4; ++r) Bs[nb][kr + 4*r][jj] = rb[r];
            }
            __syncthreads();
        }
    }
    // epilogue: j-interleaved -> coalesced stores
#pragma unroll
    for (int q = 0; q < 4; q++) {
        int jw = j0 + tx + 16*q;
        int mo = jw / Nn;
        int no = jw - mo * Nn;
        float* obase = out + (size_t)mo * Cout * Nn + no;
#pragma unroll
        for (int i = 0; i < 4; i++) {
            int dd = d0 + ty * 4 + i;
            float v = acc[0][i][q];
            if (bias)  v = __fadd_rn(v, bias[dd]);
            if (NPASS == 2) {
                float v2 = acc[1][i][q];
                if (bias2) v2 = __fadd_rn(v2, bias2[dd]);
                v = __fadd_rn(v, v2);
            }
            if (MODE == 1) v = (v >= 1.f) ? 1.f : 0.f;
            obase[(size_t)dd * Nn] = v;
        }
    }
}

// ---------------- XLA:GPU row-reduction replica (mean + var fused) ----------
// Bitwise-identical trees to the R6 passing version.
__global__ __launch_bounds__(224) void stats_k(const float* __restrict__ z, int Cout)
{
    const int c = blockIdx.x;
    const int t = threadIdx.x;
    __shared__ float sw[7];
    __shared__ float smu;
    const int lane = t & 31, w = t >> 5;
    const float* base = z + (size_t)c * Nn + t;

    // ---- mean ----
    float p = 0.f;
    if (t < Nn)
        for (int m = 0; m < TBm; ++m)
            p = __fadd_rn(p, base[(size_t)m * Cout * Nn]);
#pragma unroll
    for (int off = 16; off; off >>= 1)
        p = __fadd_rn(p, __shfl_down_sync(0xFFFFFFFFu, p, off));
    if (!lane) sw[w] = p;
    __syncthreads();
    if (w == 0) {
        float v = (lane < 7) ? sw[lane] : 0.f;
#pragma unroll
        for (int off = 16; off; off >>= 1)
            v = __fadd_rn(v, __shfl_down_sync(0xFFFFFFFFu, v, off));
        if (!lane) { smu = __fdiv_rn(v, 6272.f); g_mu[c] = smu; }
    }
    __syncthreads();
    const float mu = smu;

    // ---- var ----
    p = 0.f;
    if (t < Nn)
        for (int m = 0; m < TBm; ++m) {
            float dv = __fsub_rn(base[(size_t)m * Cout * Nn], mu);
            p = __fadd_rn(p, __fmul_rn(dv, dv));
        }
#pragma unroll
    for (int off = 16; off; off >>= 1)
        p = __fadd_rn(p, __shfl_down_sync(0xFFFFFFFFu, p, off));
    __syncthreads();
    if (!lane) sw[w] = p;
    __syncthreads();
    if (w == 0) {
        float v = (lane < 7) ? sw[lane] : 0.f;
#pragma unroll
        for (int off = 16; off; off >>= 1)
            v = __fadd_rn(v, __shfl_down_sync(0xFFFFFFFFu, v, off));
        if (!lane) {
            float var = __fdiv_rn(v, 6272.f);
            g_rs[c] = rsqrtf(__fadd_rn(var, EPSV));
        }
    }
}

// BN affine exactly as reference: ((g*(z-mu))*rs)+b, separate roundings
__device__ __forceinline__ float bn_val(float v, float g, float mu, float rs, float b)
{
    return __fadd_rn(__fmul_rn(__fmul_rn(g, __fsub_rn(v, mu)), rs), b);
}

// ---------------- BN+LIF -> 16-bit head mask (q/k/v) ----------------
__global__ __launch_bounds__(256) void spike_mask_k(
    const float* __restrict__ z, const float* __restrict__ g,
    const float* __restrict__ b, unsigned int* __restrict__ mask)
{
    int idx = blockIdx.x * 256 + threadIdx.x;     // exactly TBm*Hh*Nn threads
    int n  = idx % Nn;
    int th = idx / Nn;
    int h  = th & 15;
    int m  = th >> 4;
    const float* zb = z + (size_t)m * Cc * Nn + (size_t)h * Dd * Nn + n;
    unsigned int msk = 0;
#pragma unroll
    for (int d = 0; d < Dd; ++d) {
        int c = h * Dd + d;
        float bn = bn_val(zb[(size_t)d * Nn], g[c], g_mu[c], g_rs[c], b[c]);
        if (bn >= 1.f) msk |= (1u << d);
    }
    mask[idx] = msk;
}

// ---------------- BN+LIF elementwise (optional residual add) ----------------
__global__ __launch_bounds__(256) void spike_bn_k(
    const float* __restrict__ z, const float* __restrict__ g,
    const float* __restrict__ b, const float* __restrict__ addsrc,
    float* __restrict__ out, int Cout)
{
    int idx = blockIdx.x * 256 + threadIdx.x;
    int c = (idx / Nn) % Cout;
    float bn = bn_val(z[idx], g[c], g_mu[c], g_rs[c], b[c]);
    float s = (bn >= 1.f) ? 1.f : 0.f;
    out[idx] = addsrc ? __fadd_rn(addsrc[idx], s) : s;
}

// ---------------- attention: exact integer bit-packed (order-independent) -------
__global__ __launch_bounds__(224) void attn_k(
    const unsigned int* __restrict__ qm, const unsigned int* __restrict__ km,
    const unsigned int* __restrict__ vm, const float* __restrict__ P,
    int use_rpb, float* __restrict__ out)
{
    __shared__ unsigned int skm[Nn];
    __shared__ unsigned long long sv[Nn][4];
    __shared__ float sP[29 * 29];
    const int tbh = blockIdx.x;
    const int mb = tbh >> 4;
    const int h  = tbh & 15;
    const int base = tbh * Nn;
    const int t = threadIdx.x;
    for (int i = t; i < Nn; i += 224) {
        skm[i] = km[base + i];
        unsigned int v = vm[base + i];
#pragma unroll
        for (int w = 0; w < 4; ++w) {
            unsigned long long xL = 0;
#pragma unroll
            for (int d = 0; d < 4; ++d)
                xL |= (unsigned long long)((v >> (w * 4 + d)) & 1u) << (16 * d);
            sv[i][w] = xL;
        }
    }
    if (use_rpb)
        for (int i = t; i < 841; i += 224) sP[i] = P[i];
    __syncthreads();
    if (t >= Nn) return;

    const unsigned int q = qm[base + t];
    unsigned long long acc0 = 0, acc1 = 0, acc2 = 0, acc3 = 0;
    if (use_rpb) {
        const int ni = t / 14, nj = t - (t / 14) * 14;
        const float* prow = sP + (ni + 14) * 29 + (nj + 14);
        int m = 0;
        for (int ki = 0; ki < 14; ++ki) {
            const float* pr = prow - ki * 29;
#pragma unroll
            for (int kj = 0; kj < 14; ++kj, ++m) {
                int cnt = __popc(q & skm[m]);
                if (__fadd_rn((float)cnt, pr[-kj]) >= 1.f) {
                    acc0 += sv[m][0]; acc1 += sv[m][1];
                    acc2 += sv[m][2]; acc3 += sv[m][3];
                }
            }
        }
    } else {
#pragma unroll 4
        for (int m = 0; m < Nn; ++m) {
            unsigned long long c = (unsigned long long)__popc(q & skm[m]);
            acc0 += sv[m][0] * c; acc1 += sv[m][1] * c;
            acc2 += sv[m][2] * c; acc3 += sv[m][3] * c;
        }
    }
    float* obase = out + (size_t)mb * Cc * Nn + (size_t)h * Dd * Nn + t;
    unsigned long long accs[4] = {acc0, acc1, acc2, acc3};
#pragma unroll
    for (int w = 0; w < 4; ++w)
#pragma unroll
        for (int d4 = 0; d4 < 4; ++d4) {
            int cv = (int)((accs[w] >> (16 * d4)) & 0xFFFFULL);
            obase[(size_t)(w * 4 + d4) * Nn] = (cv >= 2) ? 1.f : 0.f;
        }
}

// ---------------- host orchestration ----------------
extern "C" void kernel_launch(void* const* d_in, const int* in_sizes, int n_in,
                              void* d_out, int out_size)
{
    const float* x     = (const float*)d_in[0];
    const float* y     = (const float*)d_in[1];
    const float* av_w  = (const float*)d_in[2];
    const float* av_g  = (const float*)d_in[3];
    const float* av_b  = (const float*)d_in[4];
    const float* va_w  = (const float*)d_in[5];
    const float* va_g  = (const float*)d_in[6];
    const float* va_b  = (const float*)d_in[7];
    const float* P_rpb = (const float*)d_in[8];
    const float* fc1_w = (const float*)d_in[9];
    const float* fc1_b = (const float*)d_in[10];
    const float* fc2_w = (const float*)d_in[11];
    const float* fc2_b = (const float*)d_in[12];
    const float* m1_w  = (const float*)d_in[13];
    const float* m1_b  = (const float*)d_in[14];
    const float* m1_g  = (const float*)d_in[15];
    const float* m1_bb = (const float*)d_in[16];
    const float* m2_w  = (const float*)d_in[17];
    const float* m2_b  = (const float*)d_in[18];
    const float* m2_g  = (const float*)d_in[19];
    const float* m2_bb = (const float*)d_in[20];
    float* out = (float*)d_out;

    float *zb, *hb, *sb, *x1b, *y1b, *curb;
    unsigned int *qmb, *kmb, *vmb;
    cudaGetSymbolAddress((void**)&zb,  g_z);
    cudaGetSymbolAddress((void**)&hb,  g_h);
    cudaGetSymbolAddress((void**)&sb,  g_s);
    cudaGetSymbolAddress((void**)&x1b, g_x1);
    cudaGetSymbolAddress((void**)&y1b, g_y1);
    cudaGetSymbolAddress((void**)&curb, g_cur);
    cudaGetSymbolAddress((void**)&qmb, g_qm);
    cudaGetSymbolAddress((void**)&kmb, g_km);
    cudaGetSymbolAddress((void**)&vmb, g_vm);

    const int nC  = TBm * Cc * Nn;     // 1,605,632
    const int nHD = TBm * HDd * Nn;    // 6,422,528

    auto gemm = [&](const float* A, const float* W, const float* bias,
                    float* o, int Cin, int Cout) {
        dim3 grid(98, Cout / 64);
        gemm_k<1, 0><<<grid, 256>>>(A, W, bias, nullptr, o, Cin, Cout, nullptr, nullptr);
    };

    auto sca = [&](const float* srcq, const float* srckv,
                   const float* W, const float* G, const float* Bt,
                   const float* rpb, const float* addbase, float* outbuf) {
        gemm(srcq, W, nullptr, zb, Cc, Cc);
        stats_k<<<Cc, 224>>>(zb, Cc);
        spike_mask_k<<<392, 256>>>(zb, G, Bt, qmb);

        gemm(srckv, W + Cc * Cc, nullptr, zb, Cc, Cc);
        stats_k<<<Cc, 224>>>(zb, Cc);
        spike_mask_k<<<392, 256>>>(zb, G + Cc, Bt + Cc, kmb);

        gemm(srckv, W + 2 * Cc * Cc, nullptr, zb, Cc, Cc);
        stats_k<<<Cc, 224>>>(zb, Cc);
        spike_mask_k<<<392, 256>>>(zb, G + 2 * Cc, Bt + 2 * Cc, vmb);

        attn_k<<<TBm * Hh, 224>>>(qmb, kmb, vmb, rpb, rpb != nullptr, sb);

        gemm(sb, W + 3 * Cc * Cc, nullptr, zb, Cc, Cc);
        stats_k<<<Cc, 224>>>(zb, Cc);
        spike_bn_k<<<nC / 256, 256>>>(zb, G + 3 * Cc, Bt + 3 * Cc, addbase, outbuf, Cc);
    };

    // x1 = x + sca(x, y, av);  y1 = y + sca(y, x, va, rpb)
    sca(x, y, av_w, av_g, av_b, nullptr, x, x1b);
    sca(y, x, va_w, va_g, va_b, P_rpb, y, y1b);

    // cur = LIF(fc1(x1) + fc2(y1))  — threshold fused into GEMM epilogue
    {
        dim3 grid(98, Cc / 64);
        gemm_k<2, 1><<<grid, 256>>>(x1b, fc1_w, fc1_b, fc2_b, curb, Cc, Cc, y1b, fc2_w);
    }

    // h = LIF(BN(m1(cur)))
    gemm(curb, m1_w, m1_b, zb, Cc, HDd);
    stats_k<<<HDd, 224>>>(zb, HDd);
    spike_bn_k<<<nHD / 256, 256>>>(zb, m1_g, m1_bb, nullptr, hb, HDd);

    // out = cur + LIF(BN(m2(h)))
    gemm(hb, m2_w, m2_b, zb, HDd, Cc);
    stats_k<<<Cc, 224>>>(zb, Cc);
    spike_bn_k<<<nC / 256, 256>>>(zb, m2_g, m2_bb, curb, out, Cc);

    (void)in_sizes; (void)n_in; (void)out_size;
}

// round 10
// speedup vs baseline: 1.5063x; 1.5063x over previous
#include <cuda_runtime.h>

// Problem constants
#define TBm 32       // T*B
#define Cc  256
#define Nn  196
#define Hh  16
#define Dd  16
#define HDd 1024
#define Jj  (TBm*Nn)     // 6272
#define EPSV 1e-5f

// ---------------- scratch (static device globals; no runtime alloc) -------------
__device__ float g_z [TBm*HDd*Nn];   // GEMM output scratch (max 1024 channels)
__device__ float g_h [TBm*HDd*Nn];   // h spikes (m1 output)
__device__ float g_s [TBm*Cc*Nn];    // attention o spikes (float 0/1)
__device__ float g_x1[TBm*Cc*Nn];
__device__ float g_y1[TBm*Cc*Nn];
__device__ float g_cur[TBm*Cc*Nn];
__device__ unsigned int g_qm[TBm*Hh*Nn];
__device__ unsigned int g_km[TBm*Hh*Nn];
__device__ unsigned int g_vm[TBm*Hh*Nn];
__device__ float g_mu[HDd];
__device__ float g_rs[HDd];

// ---------------- GEMM: out[m,d,n] = sum_c W[d,c]*A[m,c,n] ----------------
// Exact fp32, strictly ascending-k single-accumulator FMA per output element.
// Tile 64(d) x 64(j), BK=16, 256 threads, 4x4 per thread.
// Inner loop: float4 LDS for BOTH operands (2 LDS.128 + 16 FFMA per k-step).
// Two-sync single-buffer staging (R6-style).
// NPASS=2: second pair (A2,W2), separate accumulators (pass0 fully, then pass1).
// MODE=0: store raw (+bias [+bias2]); MODE=1: store (v>=1)?1:0 (fused cur LIF).
template <int NPASS, int MODE>
__global__ __launch_bounds__(256) void gemm_k(
    const float* __restrict__ A, const float* __restrict__ W,
    const float* __restrict__ bias, const float* __restrict__ bias2,
    float* __restrict__ out, int Cin, int Cout,
    const float* __restrict__ A2, const float* __restrict__ W2)
{
    __shared__ float As[16][68];
    __shared__ float Bs[16][68];
    const int t  = threadIdx.x;
    const int d0 = blockIdx.y * 64;
    const int j0 = blockIdx.x * 64;
    const int tx = t & 15;           // j group: j = j0 + tx*4 .. +3
    const int ty = t >> 4;           // d group: d = d0 + ty*4 .. +3
    // B-tile fill mapping: column jj fixed per thread
    const int jj = t & 63;
    const int kr = t >> 6;            // 0..3
    const int jB = j0 + jj;
    const int mB = jB / Nn;
    const int nB = jB - mB * Nn;
    // A-tile (weights) fill mapping
    const int kc = t & 15;
    const int ir = t >> 4;            // 0..15

    float acc[NPASS][4][4];
#pragma unroll
    for (int p = 0; p < NPASS; p++)
#pragma unroll
        for (int i = 0; i < 4; i++)
#pragma unroll
            for (int q = 0; q < 4; q++) acc[p][i][q] = 0.f;

#pragma unroll 1
    for (int pass = 0; pass < NPASS; ++pass) {
        const float* Ain = pass ? A2 : A;
        const float* Win = pass ? W2 : W;
        const float* aptr = Ain + (size_t)mB * Cin * Nn + nB;
#pragma unroll 1
        for (int c0 = 0; c0 < Cin; c0 += 16) {
            __syncthreads();
#pragma unroll
            for (int r = 0; r < 4; ++r)
                As[kc][ir + 16*r] = Win[(size_t)(d0 + ir + 16*r) * Cin + c0 + kc];
#pragma unroll
            for (int r = 0; r < 4; ++r)
                Bs[kr + 4*r][jj] = aptr[(size_t)(c0 + kr + 4*r) * Nn];
            __syncthreads();
#pragma unroll
            for (int k = 0; k < 16; ++k) {
                float4 a4 = *reinterpret_cast<const float4*>(&As[k][ty * 4]);
                float4 b4 = *reinterpret_cast<const float4*>(&Bs[k][tx * 4]);
                float a[4] = {a4.x, a4.y, a4.z, a4.w};
                float b[4] = {b4.x, b4.y, b4.z, b4.w};
#pragma unroll
                for (int i = 0; i < 4; i++)
#pragma unroll
                    for (int q = 0; q < 4; q++)
                        acc[pass][i][q] = __fmaf_rn(a[i], b[q], acc[pass][i][q]);
            }
        }
    }
    // epilogue
#pragma unroll
    for (int q = 0; q < 4; q++) {
        int jw = j0 + tx * 4 + q;
        int mo = jw / Nn;
        int no = jw - mo * Nn;
        float* obase = out + (size_t)mo * Cout * Nn + no;
#pragma unroll
        for (int i = 0; i < 4; i++) {
            int dd = d0 + ty * 4 + i;
            float v = acc[0][i][q];
            if (bias)  v = __fadd_rn(v, bias[dd]);
            if (NPASS == 2) {
                float v2 = acc[1][i][q];
                if (bias2) v2 = __fadd_rn(v2, bias2[dd]);
                v = __fadd_rn(v, v2);
            }
            if (MODE == 1) v = (v >= 1.f) ? 1.f : 0.f;
            obase[(size_t)dd * Nn] = v;
        }
    }
}

// ---------------- XLA:GPU row-reduction replica (mean + var fused) ----------
// Bitwise-identical trees to the R6 passing version.
__global__ __launch_bounds__(224) void stats_k(const float* __restrict__ z, int Cout)
{
    const int c = blockIdx.x;
    const int t = threadIdx.x;
    __shared__ float sw[7];
    __shared__ float smu;
    const int lane = t & 31, w = t >> 5;
    const float* base = z + (size_t)c * Nn + t;

    // ---- mean ----
    float p = 0.f;
    if (t < Nn)
        for (int m = 0; m < TBm; ++m)
            p = __fadd_rn(p, base[(size_t)m * Cout * Nn]);
#pragma unroll
    for (int off = 16; off; off >>= 1)
        p = __fadd_rn(p, __shfl_down_sync(0xFFFFFFFFu, p, off));
    if (!lane) sw[w] = p;
    __syncthreads();
    if (w == 0) {
        float v = (lane < 7) ? sw[lane] : 0.f;
#pragma unroll
        for (int off = 16; off; off >>= 1)
            v = __fadd_rn(v, __shfl_down_sync(0xFFFFFFFFu, v, off));
        if (!lane) { smu = __fdiv_rn(v, 6272.f); g_mu[c] = smu; }
    }
    __syncthreads();
    const float mu = smu;

    // ---- var ----
    p = 0.f;
    if (t < Nn)
        for (int m = 0; m < TBm; ++m) {
            float dv = __fsub_rn(base[(size_t)m * Cout * Nn], mu);
            p = __fadd_rn(p, __fmul_rn(dv, dv));
        }
#pragma unroll
    for (int off = 16; off; off >>= 1)
        p = __fadd_rn(p, __shfl_down_sync(0xFFFFFFFFu, p, off));
    __syncthreads();
    if (!lane) sw[w] = p;
    __syncthreads();
    if (w == 0) {
        float v = (lane < 7) ? sw[lane] : 0.f;
#pragma unroll
        for (int off = 16; off; off >>= 1)
            v = __fadd_rn(v, __shfl_down_sync(0xFFFFFFFFu, v, off));
        if (!lane) {
            float var = __fdiv_rn(v, 6272.f);
            g_rs[c] = rsqrtf(__fadd_rn(var, EPSV));
        }
    }
}

// BN affine exactly as reference: ((g*(z-mu))*rs)+b, separate roundings
__device__ __forceinline__ float bn_val(float v, float g, float mu, float rs, float b)
{
    return __fadd_rn(__fmul_rn(__fmul_rn(g, __fsub_rn(v, mu)), rs), b);
}

// ---------------- BN+LIF -> 16-bit head mask (q/k/v) ----------------
__global__ __launch_bounds__(256) void spike_mask_k(
    const float* __restrict__ z, const float* __restrict__ g,
    const float* __restrict__ b, unsigned int* __restrict__ mask)
{
    int idx = blockIdx.x * 256 + threadIdx.x;     // exactly TBm*Hh*Nn threads
    int n  = idx % Nn;
    int th = idx / Nn;
    int h  = th & 15;
    int m  = th >> 4;
    const float* zb = z + (size_t)m * Cc * Nn + (size_t)h * Dd * Nn + n;
    unsigned int msk = 0;
#pragma unroll
    for (int d = 0; d < Dd; ++d) {
        int c = h * Dd + d;
        float bn = bn_val(zb[(size_t)d * Nn], g[c], g_mu[c], g_rs[c], b[c]);
        if (bn >= 1.f) msk |= (1u << d);
    }
    mask[idx] = msk;
}

// ---------------- BN+LIF elementwise (optional residual add) ----------------
__global__ __launch_bounds__(256) void spike_bn_k(
    const float* __restrict__ z, const float* __restrict__ g,
    const float* __restrict__ b, const float* __restrict__ addsrc,
    float* __restrict__ out, int Cout)
{
    int idx = blockIdx.x * 256 + threadIdx.x;
    int c = (idx / Nn) % Cout;
    float bn = bn_val(z[idx], g[c], g_mu[c], g_rs[c], b[c]);
    float s = (bn >= 1.f) ? 1.f : 0.f;
    out[idx] = addsrc ? __fadd_rn(addsrc[idx], s) : s;
}

// ---------------- attention: exact integer bit-packed (order-independent) -------
__global__ __launch_bounds__(224) void attn_k(
    const unsigned int* __restrict__ qm, const unsigned int* __restrict__ km,
    const unsigned int* __restrict__ vm, const float* __restrict__ P,
    int use_rpb, float* __restrict__ out)
{
    __shared__ unsigned int skm[Nn];
    __shared__ unsigned long long sv[Nn][4];
    __shared__ float sP[29 * 29];
    const int tbh = blockIdx.x;
    const int mb = tbh >> 4;
    const int h  = tbh & 15;
    const int base = tbh * Nn;
    const int t = threadIdx.x;
    for (int i = t; i < Nn; i += 224) {
        skm[i] = km[base + i];
        unsigned int v = vm[base + i];
#pragma unroll
        for (int w = 0; w < 4; ++w) {
            unsigned long long xL = 0;
#pragma unroll
            for (int d = 0; d < 4; ++d)
                xL |= (unsigned long long)((v >> (w * 4 + d)) & 1u) << (16 * d);
            sv[i][w] = xL;
        }
    }
    if (use_rpb)
        for (int i = t; i < 841; i += 224) sP[i] = P[i];
    __syncthreads();
    if (t >= Nn) return;

    const unsigned int q = qm[base + t];
    unsigned long long acc0 = 0, acc1 = 0, acc2 = 0, acc3 = 0;
    if (use_rpb) {
        const int ni = t / 14, nj = t - (t / 14) * 14;
        const float* prow = sP + (ni + 14) * 29 + (nj + 14);
        int m = 0;
        for (int ki = 0; ki < 14; ++ki) {
            const float* pr = prow - ki * 29;
#pragma unroll
            for (int kj = 0; kj < 14; ++kj, ++m) {
                int cnt = __popc(q & skm[m]);
                if (__fadd_rn((float)cnt, pr[-kj]) >= 1.f) {
                    acc0 += sv[m][0]; acc1 += sv[m][1];
                    acc2 += sv[m][2]; acc3 += sv[m][3];
                }
            }
        }
    } else {
#pragma unroll 4
        for (int m = 0; m < Nn; ++m) {
            unsigned long long c = (unsigned long long)__popc(q & skm[m]);
            acc0 += sv[m][0] * c; acc1 += sv[m][1] * c;
            acc2 += sv[m][2] * c; acc3 += sv[m][3] * c;
        }
    }
    float* obase = out + (size_t)mb * Cc * Nn + (size_t)h * Dd * Nn + t;
    unsigned long long accs[4] = {acc0, acc1, acc2, acc3};
#pragma unroll
    for (int w = 0; w < 4; ++w)
#pragma unroll
        for (int d4 = 0; d4 < 4; ++d4) {
            int cv = (int)((accs[w] >> (16 * d4)) & 0xFFFFULL);
            obase[(size_t)(w * 4 + d4) * Nn] = (cv >= 2) ? 1.f : 0.f;
        }
}

// ---------------- host orchestration ----------------
extern "C" void kernel_launch(void* const* d_in, const int* in_sizes, int n_in,
                              void* d_out, int out_size)
{
    const float* x     = (const float*)d_in[0];
    const float* y     = (const float*)d_in[1];
    const float* av_w  = (const float*)d_in[2];
    const float* av_g  = (const float*)d_in[3];
    const float* av_b  = (const float*)d_in[4];
    const float* va_w  = (const float*)d_in[5];
    const float* va_g  = (const float*)d_in[6];
    const float* va_b  = (const float*)d_in[7];
    const float* P_rpb = (const float*)d_in[8];
    const float* fc1_w = (const float*)d_in[9];
    const float* fc1_b = (const float*)d_in[10];
    const float* fc2_w = (const float*)d_in[11];
    const float* fc2_b = (const float*)d_in[12];
    const float* m1_w  = (const float*)d_in[13];
    const float* m1_b  = (const float*)d_in[14];
    const float* m1_g  = (const float*)d_in[15];
    const float* m1_bb = (const float*)d_in[16];
    const float* m2_w  = (const float*)d_in[17];
    const float* m2_b  = (const float*)d_in[18];
    const float* m2_g  = (const float*)d_in[19];
    const float* m2_bb = (const float*)d_in[20];
    float* out = (float*)d_out;

    float *zb, *hb, *sb, *x1b, *y1b, *curb;
    unsigned int *qmb, *kmb, *vmb;
    cudaGetSymbolAddress((void**)&zb,  g_z);
    cudaGetSymbolAddress((void**)&hb,  g_h);
    cudaGetSymbolAddress((void**)&sb,  g_s);
    cudaGetSymbolAddress((void**)&x1b, g_x1);
    cudaGetSymbolAddress((void**)&y1b, g_y1);
    cudaGetSymbolAddress((void**)&curb, g_cur);
    cudaGetSymbolAddress((void**)&qmb, g_qm);
    cudaGetSymbolAddress((void**)&kmb, g_km);
    cudaGetSymbolAddress((void**)&vmb, g_vm);

    const int nC  = TBm * Cc * Nn;     // 1,605,632
    const int nHD = TBm * HDd * Nn;    // 6,422,528

    auto gemm = [&](const float* A, const float* W, const float* bias,
                    float* o, int Cin, int Cout) {
        dim3 grid(98, Cout / 64);
        gemm_k<1, 0><<<grid, 256>>>(A, W, bias, nullptr, o, Cin, Cout, nullptr, nullptr);
    };

    auto sca = [&](const float* srcq, const float* srckv,
                   const float* W, const float* G, const float* Bt,
                   const float* rpb, const float* addbase, float* outbuf) {
        gemm(srcq, W, nullptr, zb, Cc, Cc);
        stats_k<<<Cc, 224>>>(zb, Cc);
        spike_mask_k<<<392, 256>>>(zb, G, Bt, qmb);

        gemm(srckv, W + Cc * Cc, nullptr, zb, Cc, Cc);
        stats_k<<<Cc, 224>>>(zb, Cc);
        spike_mask_k<<<392, 256>>>(zb, G + Cc, Bt + Cc, kmb);

        gemm(srckv, W + 2 * Cc * Cc, nullptr, zb, Cc, Cc);
        stats_k<<<Cc, 224>>>(zb, Cc);
        spike_mask_k<<<392, 256>>>(zb, G + 2 * Cc, Bt + 2 * Cc, vmb);

        attn_k<<<TBm * Hh, 224>>>(qmb, kmb, vmb, rpb, rpb != nullptr, sb);

        gemm(sb, W + 3 * Cc * Cc, nullptr, zb, Cc, Cc);
        stats_k<<<Cc, 224>>>(zb, Cc);
        spike_bn_k<<<nC / 256, 256>>>(zb, G + 3 * Cc, Bt + 3 * Cc, addbase, outbuf, Cc);
    };

    // x1 = x + sca(x, y, av);  y1 = y + sca(y, x, va, rpb)
    sca(x, y, av_w, av_g, av_b, nullptr, x, x1b);
    sca(y, x, va_w, va_g, va_b, P_rpb, y, y1b);

    // cur = LIF(fc1(x1) + fc2(y1))  — threshold fused into GEMM epilogue
    {
        dim3 grid(98, Cc / 64);
        gemm_k<2, 1><<<grid, 256>>>(x1b, fc1_w, fc1_b, fc2_b, curb, Cc, Cc, y1b, fc2_w);
    }

    // h = LIF(BN(m1(cur)))
    gemm(curb, m1_w, m1_b, zb, Cc, HDd);
    stats_k<<<HDd, 224>>>(zb, HDd);
    spike_bn_k<<<nHD / 256, 256>>>(zb, m1_g, m1_bb, nullptr, hb, HDd);

    // out = cur + LIF(BN(m2(h)))
    gemm(hb, m2_w, m2_b, zb, HDd, Cc);
    stats_k<<<Cc, 224>>>(zb, Cc);
    spike_bn_k<<<nC / 256, 256>>>(zb, m2_g, m2_bb, curb, out, Cc);

    (void)in_sizes; (void)n_in; (void)out_size;
}

// round 11
// speedup vs baseline: 1.5394x; 1.0220x over previous
#include <cuda_runtime.h>

// Problem constants
#define TBm 32       // T*B
#define Cc  256
#define Nn  196
#define Hh  16
#define Dd  16
#define HDd 1024
#define Jj  (TBm*Nn)     // 6272
#define EPSV 1e-5f

// ---------------- scratch (static device globals; no runtime alloc) -------------
__device__ float g_z [TBm*HDd*Nn];   // GEMM output scratch (max 1024 channels)
__device__ float g_h [TBm*HDd*Nn];   // h spikes (m1 output)
__device__ float g_s [TBm*Cc*Nn];    // attention o spikes (float 0/1)
__device__ float g_x1[TBm*Cc*Nn];
__device__ float g_y1[TBm*Cc*Nn];
__device__ float g_cur[TBm*Cc*Nn];
__device__ unsigned int g_qm[TBm*Hh*Nn];
__device__ unsigned int g_km[TBm*Hh*Nn];
__device__ unsigned int g_vm[TBm*Hh*Nn];
__device__ float g_mu[HDd];
__device__ float g_rs[HDd];

// ---------------- GEMM: out[m,d,n] = sum_c W[d,c]*A[m,c,n] ----------------
// Exact fp32, strictly ascending-k single-accumulator FMA per output element.
// Tile 64(d) x 64(j), BK=32, 256 threads, 4x4 per thread.
// Inner loop: float4 LDS both operands (2 LDS.128 + 16 FFMA per k-step).
// Register prefetch of stage s+1 issued before computing stage s (single smem
// buffer, 2 syncs/stage but gmem latency hidden behind the 32-k compute).
// NPASS=2: second pair (A2,W2), separate accumulators (pass0 fully, then pass1).
// MODE=0: store raw (+bias [+bias2]); MODE=1: store (v>=1)?1:0 (fused cur LIF).
template <int NPASS, int MODE>
__global__ __launch_bounds__(256) void gemm_k(
    const float* __restrict__ A, const float* __restrict__ W,
    const float* __restrict__ bias, const float* __restrict__ bias2,
    float* __restrict__ out, int Cin, int Cout,
    const float* __restrict__ A2, const float* __restrict__ W2)
{
    __shared__ float As[32][68];
    __shared__ float Bs[32][68];
    const int t  = threadIdx.x;
    const int d0 = blockIdx.y * 64;
    const int j0 = blockIdx.x * 64;
    const int tx = t & 15;           // j group: j = j0 + tx*4 .. +3
    const int ty = t >> 4;           // d group: d = d0 + ty*4 .. +3
    // B-tile fill mapping: column jj fixed per thread
    const int jj = t & 63;
    const int kr = t >> 6;           // 0..3 (k rows kr+4*r, r<8)
    const int jB = j0 + jj;
    const int mB = jB / Nn;
    const int nB = jB - mB * Nn;
    // A-tile (weights) fill mapping
    const int kc = t & 31;           // k column
    const int dr = t >> 5;           // 0..7 (d rows dr+8*r, r<8)

    float acc[NPASS][4][4];
#pragma unroll
    for (int p = 0; p < NPASS; p++)
#pragma unroll
        for (int i = 0; i < 4; i++)
#pragma unroll
            for (int q = 0; q < 4; q++) acc[p][i][q] = 0.f;

    float wreg[8], breg[8];

#pragma unroll 1
    for (int pass = 0; pass < NPASS; ++pass) {
        const float* Ain = pass ? A2 : A;
        const float* Win = pass ? W2 : W;
        const float* aptr = Ain + (size_t)mB * Cin * Nn + nB;
        const int nst = Cin >> 5;

        // prefetch stage 0
#pragma unroll
        for (int r = 0; r < 8; ++r)
            wreg[r] = Win[(size_t)(d0 + dr + 8*r) * Cin + kc];
#pragma unroll
        for (int r = 0; r < 8; ++r)
            breg[r] = aptr[(size_t)(kr + 4*r) * Nn];

#pragma unroll 1
        for (int s = 0; s < nst; ++s) {
            __syncthreads();     // previous compute done; smem reusable
#pragma unroll
            for (int r = 0; r < 8; ++r) As[kc][dr + 8*r] = wreg[r];
#pragma unroll
            for (int r = 0; r < 8; ++r) Bs[kr + 4*r][jj] = breg[r];
            __syncthreads();

            if (s + 1 < nst) {   // issue next-stage loads early
                const int c0 = (s + 1) << 5;
#pragma unroll
                for (int r = 0; r < 8; ++r)
                    wreg[r] = Win[(size_t)(d0 + dr + 8*r) * Cin + c0 + kc];
#pragma unroll
                for (int r = 0; r < 8; ++r)
                    breg[r] = aptr[(size_t)(c0 + kr + 4*r) * Nn];
            }
            // compute stage s (ascending k; single accumulator)
#pragma unroll
            for (int k = 0; k < 32; ++k) {
                float4 a4 = *reinterpret_cast<const float4*>(&As[k][ty * 4]);
                float4 b4 = *reinterpret_cast<const float4*>(&Bs[k][tx * 4]);
                float a[4] = {a4.x, a4.y, a4.z, a4.w};
                float b[4] = {b4.x, b4.y, b4.z, b4.w};
#pragma unroll
                for (int i = 0; i < 4; i++)
#pragma unroll
                    for (int q = 0; q < 4; q++)
                        acc[pass][i][q] = __fmaf_rn(a[i], b[q], acc[pass][i][q]);
            }
        }
    }
    // epilogue
#pragma unroll
    for (int q = 0; q < 4; q++) {
        int jw = j0 + tx * 4 + q;
        int mo = jw / Nn;
        int no = jw - mo * Nn;
        float* obase = out + (size_t)mo * Cout * Nn + no;
#pragma unroll
        for (int i = 0; i < 4; i++) {
            int dd = d0 + ty * 4 + i;
            float v = acc[0][i][q];
            if (bias)  v = __fadd_rn(v, bias[dd]);
            if (NPASS == 2) {
                float v2 = acc[1][i][q];
                if (bias2) v2 = __fadd_rn(v2, bias2[dd]);
                v = __fadd_rn(v, v2);
            }
            if (MODE == 1) v = (v >= 1.f) ? 1.f : 0.f;
            obase[(size_t)dd * Nn] = v;
        }
    }
}

// ---------------- XLA:GPU row-reduction replica (mean + var fused) ----------
// Bitwise-identical trees to the R6 passing version.
__global__ __launch_bounds__(224) void stats_k(const float* __restrict__ z, int Cout)
{
    const int c = blockIdx.x;
    const int t = threadIdx.x;
    __shared__ float sw[7];
    __shared__ float smu;
    const int lane = t & 31, w = t >> 5;
    const float* base = z + (size_t)c * Nn + t;

    // ---- mean ----
    float p = 0.f;
    if (t < Nn)
        for (int m = 0; m < TBm; ++m)
            p = __fadd_rn(p, base[(size_t)m * Cout * Nn]);
#pragma unroll
    for (int off = 16; off; off >>= 1)
        p = __fadd_rn(p, __shfl_down_sync(0xFFFFFFFFu, p, off));
    if (!lane) sw[w] = p;
    __syncthreads();
    if (w == 0) {
        float v = (lane < 7) ? sw[lane] : 0.f;
#pragma unroll
        for (int off = 16; off; off >>= 1)
            v = __fadd_rn(v, __shfl_down_sync(0xFFFFFFFFu, v, off));
        if (!lane) { smu = __fdiv_rn(v, 6272.f); g_mu[c] = smu; }
    }
    __syncthreads();
    const float mu = smu;

    // ---- var ----
    p = 0.f;
    if (t < Nn)
        for (int m = 0; m < TBm; ++m) {
            float dv = __fsub_rn(base[(size_t)m * Cout * Nn], mu);
            p = __fadd_rn(p, __fmul_rn(dv, dv));
        }
#pragma unroll
    for (int off = 16; off; off >>= 1)
        p = __fadd_rn(p, __shfl_down_sync(0xFFFFFFFFu, p, off));
    __syncthreads();
    if (!lane) sw[w] = p;
    __syncthreads();
    if (w == 0) {
        float v = (lane < 7) ? sw[lane] : 0.f;
#pragma unroll
        for (int off = 16; off; off >>= 1)
            v = __fadd_rn(v, __shfl_down_sync(0xFFFFFFFFu, v, off));
        if (!lane) {
            float var = __fdiv_rn(v, 6272.f);
            g_rs[c] = rsqrtf(__fadd_rn(var, EPSV));
        }
    }
}

// BN affine exactly as reference: ((g*(z-mu))*rs)+b, separate roundings
__device__ __forceinline__ float bn_val(float v, float g, float mu, float rs, float b)
{
    return __fadd_rn(__fmul_rn(__fmul_rn(g, __fsub_rn(v, mu)), rs), b);
}

// ---------------- BN+LIF -> 16-bit head mask (q/k/v) ----------------
__global__ __launch_bounds__(256) void spike_mask_k(
    const float* __restrict__ z, const float* __restrict__ g,
    const float* __restrict__ b, unsigned int* __restrict__ mask)
{
    int idx = blockIdx.x * 256 + threadIdx.x;     // exactly TBm*Hh*Nn threads
    int n  = idx % Nn;
    int th = idx / Nn;
    int h  = th & 15;
    int m  = th >> 4;
    const float* zb = z + (size_t)m * Cc * Nn + (size_t)h * Dd * Nn + n;
    unsigned int msk = 0;
#pragma unroll
    for (int d = 0; d < Dd; ++d) {
        int c = h * Dd + d;
        float bn = bn_val(zb[(size_t)d * Nn], g[c], g_mu[c], g_rs[c], b[c]);
        if (bn >= 1.f) msk |= (1u << d);
    }
    mask[idx] = msk;
}

// ---------------- BN+LIF elementwise (optional residual add) ----------------
__global__ __launch_bounds__(256) void spike_bn_k(
    const float* __restrict__ z, const float* __restrict__ g,
    const float* __restrict__ b, const float* __restrict__ addsrc,
    float* __restrict__ out, int Cout)
{
    int idx = blockIdx.x * 256 + threadIdx.x;
    int c = (idx / Nn) % Cout;
    float bn = bn_val(z[idx], g[c], g_mu[c], g_rs[c], b[c]);
    float s = (bn >= 1.f) ? 1.f : 0.f;
    out[idx] = addsrc ? __fadd_rn(addsrc[idx], s) : s;
}

// ---------------- attention: exact integer bit-packed (order-independent) -------
__global__ __launch_bounds__(224) void attn_k(
    const unsigned int* __restrict__ qm, const unsigned int* __restrict__ km,
    const unsigned int* __restrict__ vm, const float* __restrict__ P,
    int use_rpb, float* __restrict__ out)
{
    __shared__ unsigned int skm[Nn];
    __shared__ unsigned long long sv[Nn][4];
    __shared__ float sP[29 * 29];
    const int tbh = blockIdx.x;
    const int mb = tbh >> 4;
    const int h  = tbh & 15;
    const int base = tbh * Nn;
    const int t = threadIdx.x;
    for (int i = t; i < Nn; i += 224) {
        skm[i] = km[base + i];
        unsigned int v = vm[base + i];
#pragma unroll
        for (int w = 0; w < 4; ++w) {
            unsigned long long xL = 0;
#pragma unroll
            for (int d = 0; d < 4; ++d)
                xL |= (unsigned long long)((v >> (w * 4 + d)) & 1u) << (16 * d);
            sv[i][w] = xL;
        }
    }
    if (use_rpb)
        for (int i = t; i < 841; i += 224) sP[i] = P[i];
    __syncthreads();
    if (t >= Nn) return;

    const unsigned int q = qm[base + t];
    unsigned long long acc0 = 0, acc1 = 0, acc2 = 0, acc3 = 0;
    if (use_rpb) {
        const int ni = t / 14, nj = t - (t / 14) * 14;
        const float* prow = sP + (ni + 14) * 29 + (nj + 14);
        int m = 0;
        for (int ki = 0; ki < 14; ++ki) {
            const float* pr = prow - ki * 29;
#pragma unroll
            for (int kj = 0; kj < 14; ++kj, ++m) {
                int cnt = __popc(q & skm[m]);
                if (__fadd_rn((float)cnt, pr[-kj]) >= 1.f) {
                    acc0 += sv[m][0]; acc1 += sv[m][1];
                    acc2 += sv[m][2]; acc3 += sv[m][3];
                }
            }
        }
    } else {
#pragma unroll 4
        for (int m = 0; m < Nn; ++m) {
            unsigned long long c = (unsigned long long)__popc(q & skm[m]);
            acc0 += sv[m][0] * c; acc1 += sv[m][1] * c;
            acc2 += sv[m][2] * c; acc3 += sv[m][3] * c;
        }
    }
    float* obase = out + (size_t)mb * Cc * Nn + (size_t)h * Dd * Nn + t;
    unsigned long long accs[4] = {acc0, acc1, acc2, acc3};
#pragma unroll
    for (int w = 0; w < 4; ++w)
#pragma unroll
        for (int d4 = 0; d4 < 4; ++d4) {
            int cv = (int)((accs[w] >> (16 * d4)) & 0xFFFFULL);
            obase[(size_t)(w * 4 + d4) * Nn] = (cv >= 2) ? 1.f : 0.f;
        }
}

// ---------------- host orchestration ----------------
extern "C" void kernel_launch(void* const* d_in, const int* in_sizes, int n_in,
                              void* d_out, int out_size)
{
    const float* x     = (const float*)d_in[0];
    const float* y     = (const float*)d_in[1];
    const float* av_w  = (const float*)d_in[2];
    const float* av_g  = (const float*)d_in[3];
    const float* av_b  = (const float*)d_in[4];
    const float* va_w  = (const float*)d_in[5];
    const float* va_g  = (const float*)d_in[6];
    const float* va_b  = (const float*)d_in[7];
    const float* P_rpb = (const float*)d_in[8];
    const float* fc1_w = (const float*)d_in[9];
    const float* fc1_b = (const float*)d_in[10];
    const float* fc2_w = (const float*)d_in[11];
    const float* fc2_b = (const float*)d_in[12];
    const float* m1_w  = (const float*)d_in[13];
    const float* m1_b  = (const float*)d_in[14];
    const float* m1_g  = (const float*)d_in[15];
    const float* m1_bb = (const float*)d_in[16];
    const float* m2_w  = (const float*)d_in[17];
    const float* m2_b  = (const float*)d_in[18];
    const float* m2_g  = (const float*)d_in[19];
    const float* m2_bb = (const float*)d_in[20];
    float* out = (float*)d_out;

    float *zb, *hb, *sb, *x1b, *y1b, *curb;
    unsigned int *qmb, *kmb, *vmb;
    cudaGetSymbolAddress((void**)&zb,  g_z);
    cudaGetSymbolAddress((void**)&hb,  g_h);
    cudaGetSymbolAddress((void**)&sb,  g_s);
    cudaGetSymbolAddress((void**)&x1b, g_x1);
    cudaGetSymbolAddress((void**)&y1b, g_y1);
    cudaGetSymbolAddress((void**)&curb, g_cur);
    cudaGetSymbolAddress((void**)&qmb, g_qm);
    cudaGetSymbolAddress((void**)&kmb, g_km);
    cudaGetSymbolAddress((void**)&vmb, g_vm);

    const int nC  = TBm * Cc * Nn;     // 1,605,632
    const int nHD = TBm * HDd * Nn;    // 6,422,528

    auto gemm = [&](const float* A, const float* W, const float* bias,
                    float* o, int Cin, int Cout) {
        dim3 grid(98, Cout / 64);
        gemm_k<1, 0><<<grid, 256>>>(A, W, bias, nullptr, o, Cin, Cout, nullptr, nullptr);
    };

    auto sca = [&](const float* srcq, const float* srckv,
                   const float* W, const float* G, const float* Bt,
                   const float* rpb, const float* addbase, float* outbuf) {
        gemm(srcq, W, nullptr, zb, Cc, Cc);
        stats_k<<<Cc, 224>>>(zb, Cc);
        spike_mask_k<<<392, 256>>>(zb, G, Bt, qmb);

        gemm(srckv, W + Cc * Cc, nullptr, zb, Cc, Cc);
        stats_k<<<Cc, 224>>>(zb, Cc);
        spike_mask_k<<<392, 256>>>(zb, G + Cc, Bt + Cc, kmb);

        gemm(srckv, W + 2 * Cc * Cc, nullptr, zb, Cc, Cc);
        stats_k<<<Cc, 224>>>(zb, Cc);
        spike_mask_k<<<392, 256>>>(zb, G + 2 * Cc, Bt + 2 * Cc, vmb);

        attn_k<<<TBm * Hh, 224>>>(qmb, kmb, vmb, rpb, rpb != nullptr, sb);

        gemm(sb, W + 3 * Cc * Cc, nullptr, zb, Cc, Cc);
        stats_k<<<Cc, 224>>>(zb, Cc);
        spike_bn_k<<<nC / 256, 256>>>(zb, G + 3 * Cc, Bt + 3 * Cc, addbase, outbuf, Cc);
    };

    // x1 = x + sca(x, y, av);  y1 = y + sca(y, x, va, rpb)
    sca(x, y, av_w, av_g, av_b, nullptr, x, x1b);
    sca(y, x, va_w, va_g, va_b, P_rpb, y, y1b);

    // cur = LIF(fc1(x1) + fc2(y1))  — threshold fused into GEMM epilogue
    {
        dim3 grid(98, Cc / 64);
        gemm_k<2, 1><<<grid, 256>>>(x1b, fc1_w, fc1_b, fc2_b, curb, Cc, Cc, y1b, fc2_w);
    }

    // h = LIF(BN(m1(cur)))
    gemm(curb, m1_w, m1_b, zb, Cc, HDd);
    stats_k<<<HDd, 224>>>(zb, HDd);
    spike_bn_k<<<nHD / 256, 256>>>(zb, m1_g, m1_bb, nullptr, hb, HDd);

    // out = cur + LIF(BN(m2(h)))
    gemm(hb, m2_w, m2_b, zb, HDd, Cc);
    stats_k<<<Cc, 224>>>(zb, Cc);
    spike_bn_k<<<nC / 256, 256>>>(zb, m2_g, m2_bb, curb, out, Cc);

    (void)in_sizes; (void)n_in; (void)out_size;
}

// round 12
// speedup vs baseline: 1.6235x; 1.0546x over previous
#include <cuda_runtime.h>

// Problem constants
#define TBm 32       // T*B
#define Cc  256
#define Nn  196
#define Hh  16
#define Dd  16
#define HDd 1024
#define Jj  (TBm*Nn)     // 6272
#define EPSV 1e-5f

// ---------------- scratch (static device globals; no runtime alloc) -------------
__device__ float g_z [TBm*HDd*Nn];   // GEMM output scratch (max 1024 channels)
__device__ float g_h [TBm*HDd*Nn];   // h spikes (m1 output)
__device__ float g_s [TBm*Cc*Nn];    // attention o spikes (float 0/1)
__device__ float g_x1[TBm*Cc*Nn];
__device__ float g_y1[TBm*Cc*Nn];
__device__ float g_cur[TBm*Cc*Nn];
__device__ unsigned int g_qm[TBm*Hh*Nn];
__device__ unsigned int g_km[TBm*Hh*Nn];
__device__ unsigned int g_vm[TBm*Hh*Nn];
__device__ float g_mu[HDd];
__device__ float g_rs[HDd];

// ---------------- GEMM: out[m,d,n] = sum_c W[d,c]*A[m,c,n] ----------------
// Exact fp32, strictly ascending-k single-accumulator FMA per output element.
// Tile 64(d) x 64(j), BK=16, 128 threads, 8x4 per thread.
// Inner loop: 3 LDS.128 + 32 FFMA per k-step (91% FFMA mix, 10 smem-B/FFMA).
// Register prefetch of stage s+1 before computing stage s.
// NPASS=2: second pair (A2,W2), separate accumulators (pass0 fully, then pass1).
// MODE=0: store raw (+bias [+bias2]); MODE=1: store (v>=1)?1:0 (fused cur LIF).
template <int NPASS, int MODE>
__global__ __launch_bounds__(128) void gemm_k(
    const float* __restrict__ A, const float* __restrict__ W,
    const float* __restrict__ bias, const float* __restrict__ bias2,
    float* __restrict__ out, int Cin, int Cout,
    const float* __restrict__ A2, const float* __restrict__ W2)
{
    __shared__ float As[16][68];
    __shared__ float Bs[16][68];
    const int t  = threadIdx.x;
    const int d0 = blockIdx.y * 64;
    const int j0 = blockIdx.x * 64;
    const int tx = t & 15;           // j group: j = j0 + tx*4 .. +3
    const int ty = t >> 4;           // d group: d = d0 + ty*8 .. +7 (0..7)
    // B-tile fill mapping: column jj fixed per thread
    const int jj = t & 63;
    const int kr = t >> 6;           // 0..1  (k rows kr + 2*r, r<8)
    const int jB = j0 + jj;
    const int mB = jB / Nn;
    const int nB = jB - mB * Nn;
    // A-tile (weights) fill mapping
    const int kc = t & 15;           // k column
    const int dr = t >> 4;           // 0..7  (d rows dr + 8*r, r<8)

    float acc[NPASS][8][4];
#pragma unroll
    for (int p = 0; p < NPASS; p++)
#pragma unroll
        for (int i = 0; i < 8; i++)
#pragma unroll
            for (int q = 0; q < 4; q++) acc[p][i][q] = 0.f;

    float wreg[8], breg[8];

#pragma unroll 1
    for (int pass = 0; pass < NPASS; ++pass) {
        const float* Ain = pass ? A2 : A;
        const float* Win = pass ? W2 : W;
        const float* aptr = Ain + (size_t)mB * Cin * Nn + nB;
        const int nst = Cin >> 4;

        // prefetch stage 0
#pragma unroll
        for (int r = 0; r < 8; ++r)
            wreg[r] = Win[(size_t)(d0 + dr + 8*r) * Cin + kc];
#pragma unroll
        for (int r = 0; r < 8; ++r)
            breg[r] = aptr[(size_t)(kr + 2*r) * Nn];

#pragma unroll 1
        for (int s = 0; s < nst; ++s) {
            __syncthreads();     // previous compute done; smem reusable
#pragma unroll
            for (int r = 0; r < 8; ++r) As[kc][dr + 8*r] = wreg[r];
#pragma unroll
            for (int r = 0; r < 8; ++r) Bs[kr + 2*r][jj] = breg[r];
            __syncthreads();

            if (s + 1 < nst) {   // issue next-stage loads early
                const int c0 = (s + 1) << 4;
#pragma unroll
                for (int r = 0; r < 8; ++r)
                    wreg[r] = Win[(size_t)(d0 + dr + 8*r) * Cin + c0 + kc];
#pragma unroll
                for (int r = 0; r < 8; ++r)
                    breg[r] = aptr[(size_t)(c0 + kr + 2*r) * Nn];
            }
            // compute stage s (ascending k; single accumulator)
#pragma unroll
            for (int k = 0; k < 16; ++k) {
                float4 a0 = *reinterpret_cast<const float4*>(&As[k][ty * 8]);
                float4 a1 = *reinterpret_cast<const float4*>(&As[k][ty * 8 + 4]);
                float4 b4 = *reinterpret_cast<const float4*>(&Bs[k][tx * 4]);
                float a[8] = {a0.x, a0.y, a0.z, a0.w, a1.x, a1.y, a1.z, a1.w};
                float b[4] = {b4.x, b4.y, b4.z, b4.w};
#pragma unroll
                for (int i = 0; i < 8; i++)
#pragma unroll
                    for (int q = 0; q < 4; q++)
                        acc[pass][i][q] = __fmaf_rn(a[i], b[q], acc[pass][i][q]);
            }
        }
    }
    // epilogue
#pragma unroll
    for (int q = 0; q < 4; q++) {
        int jw = j0 + tx * 4 + q;
        int mo = jw / Nn;
        int no = jw - mo * Nn;
        float* obase = out + (size_t)mo * Cout * Nn + no;
#pragma unroll
        for (int i = 0; i < 8; i++) {
            int dd = d0 + ty * 8 + i;
            float v = acc[0][i][q];
            if (bias)  v = __fadd_rn(v, bias[dd]);
            if (NPASS == 2) {
                float v2 = acc[1][i][q];
                if (bias2) v2 = __fadd_rn(v2, bias2[dd]);
                v = __fadd_rn(v, v2);
            }
            if (MODE == 1) v = (v >= 1.f) ? 1.f : 0.f;
            obase[(size_t)dd * Nn] = v;
        }
    }
}

// ---------------- XLA:GPU row-reduction replica (mean + var fused) ----------
// Bitwise-identical trees to the R6 passing version.
__global__ __launch_bounds__(224) void stats_k(const float* __restrict__ z, int Cout)
{
    const int c = blockIdx.x;
    const int t = threadIdx.x;
    __shared__ float sw[7];
    __shared__ float smu;
    const int lane = t & 31, w = t >> 5;
    const float* base = z + (size_t)c * Nn + t;

    // ---- mean ----
    float p = 0.f;
    if (t < Nn)
        for (int m = 0; m < TBm; ++m)
            p = __fadd_rn(p, base[(size_t)m * Cout * Nn]);
#pragma unroll
    for (int off = 16; off; off >>= 1)
        p = __fadd_rn(p, __shfl_down_sync(0xFFFFFFFFu, p, off));
    if (!lane) sw[w] = p;
    __syncthreads();
    if (w == 0) {
        float v = (lane < 7) ? sw[lane] : 0.f;
#pragma unroll
        for (int off = 16; off; off >>= 1)
            v = __fadd_rn(v, __shfl_down_sync(0xFFFFFFFFu, v, off));
        if (!lane) { smu = __fdiv_rn(v, 6272.f); g_mu[c] = smu; }
    }
    __syncthreads();
    const float mu = smu;

    // ---- var ----
    p = 0.f;
    if (t < Nn)
        for (int m = 0; m < TBm; ++m) {
            float dv = __fsub_rn(base[(size_t)m * Cout * Nn], mu);
            p = __fadd_rn(p, __fmul_rn(dv, dv));
        }
#pragma unroll
    for (int off = 16; off; off >>= 1)
        p = __fadd_rn(p, __shfl_down_sync(0xFFFFFFFFu, p, off));
    __syncthreads();
    if (!lane) sw[w] = p;
    __syncthreads();
    if (w == 0) {
        float v = (lane < 7) ? sw[lane] : 0.f;
#pragma unroll
        for (int off = 16; off; off >>= 1)
            v = __fadd_rn(v, __shfl_down_sync(0xFFFFFFFFu, v, off));
        if (!lane) {
            float var = __fdiv_rn(v, 6272.f);
            g_rs[c] = rsqrtf(__fadd_rn(var, EPSV));
        }
    }
}

// BN affine exactly as reference: ((g*(z-mu))*rs)+b, separate roundings
__device__ __forceinline__ float bn_val(float v, float g, float mu, float rs, float b)
{
    return __fadd_rn(__fmul_rn(__fmul_rn(g, __fsub_rn(v, mu)), rs), b);
}

// ---------------- BN+LIF -> 16-bit head mask (q/k/v) ----------------
__global__ __launch_bounds__(256) void spike_mask_k(
    const float* __restrict__ z, const float* __restrict__ g,
    const float* __restrict__ b, unsigned int* __restrict__ mask)
{
    int idx = blockIdx.x * 256 + threadIdx.x;     // exactly TBm*Hh*Nn threads
    int n  = idx % Nn;
    int th = idx / Nn;
    int h  = th & 15;
    int m  = th >> 4;
    const float* zb = z + (size_t)m * Cc * Nn + (size_t)h * Dd * Nn + n;
    unsigned int msk = 0;
#pragma unroll
    for (int d = 0; d < Dd; ++d) {
        int c = h * Dd + d;
        float bn = bn_val(zb[(size_t)d * Nn], g[c], g_mu[c], g_rs[c], b[c]);
        if (bn >= 1.f) msk |= (1u << d);
    }
    mask[idx] = msk;
}

// ---------------- BN+LIF elementwise (optional residual add) ----------------
__global__ __launch_bounds__(256) void spike_bn_k(
    const float* __restrict__ z, const float* __restrict__ g,
    const float* __restrict__ b, const float* __restrict__ addsrc,
    float* __restrict__ out, int Cout)
{
    int idx = blockIdx.x * 256 + threadIdx.x;
    int c = (idx / Nn) % Cout;
    float bn = bn_val(z[idx], g[c], g_mu[c], g_rs[c], b[c]);
    float s = (bn >= 1.f) ? 1.f : 0.f;
    out[idx] = addsrc ? __fadd_rn(addsrc[idx], s) : s;
}

// ---------------- attention: exact integer bit-packed (order-independent) -------
__global__ __launch_bounds__(224) void attn_k(
    const unsigned int* __restrict__ qm, const unsigned int* __restrict__ km,
    const unsigned int* __restrict__ vm, const float* __restrict__ P,
    int use_rpb, float* __restrict__ out)
{
    __shared__ unsigned int skm[Nn];
    __shared__ unsigned long long sv[Nn][4];
    __shared__ float sP[29 * 29];
    const int tbh = blockIdx.x;
    const int mb = tbh >> 4;
    const int h  = tbh & 15;
    const int base = tbh * Nn;
    const int t = threadIdx.x;
    for (int i = t; i < Nn; i += 224) {
        skm[i] = km[base + i];
        unsigned int v = vm[base + i];
#pragma unroll
        for (int w = 0; w < 4; ++w) {
            unsigned long long xL = 0;
#pragma unroll
            for (int d = 0; d < 4; ++d)
                xL |= (unsigned long long)((v >> (w * 4 + d)) & 1u) << (16 * d);
            sv[i][w] = xL;
        }
    }
    if (use_rpb)
        for (int i = t; i < 841; i += 224) sP[i] = P[i];
    __syncthreads();
    if (t >= Nn) return;

    const unsigned int q = qm[base + t];
    unsigned long long acc0 = 0, acc1 = 0, acc2 = 0, acc3 = 0;
    if (use_rpb) {
        const int ni = t / 14, nj = t - (t / 14) * 14;
        const float* prow = sP + (ni + 14) * 29 + (nj + 14);
        int m = 0;
        for (int ki = 0; ki < 14; ++ki) {
            const float* pr = prow - ki * 29;
#pragma unroll
            for (int kj = 0; kj < 14; ++kj, ++m) {
                int cnt = __popc(q & skm[m]);
                if (__fadd_rn((float)cnt, pr[-kj]) >= 1.f) {
                    acc0 += sv[m][0]; acc1 += sv[m][1];
                    acc2 += sv[m][2]; acc3 += sv[m][3];
                }
            }
        }
    } else {
#pragma unroll 4
        for (int m = 0; m < Nn; ++m) {
            unsigned long long c = (unsigned long long)__popc(q & skm[m]);
            acc0 += sv[m][0] * c; acc1 += sv[m][1] * c;
            acc2 += sv[m][2] * c; acc3 += sv[m][3] * c;
        }
    }
    float* obase = out + (size_t)mb * Cc * Nn + (size_t)h * Dd * Nn + t;
    unsigned long long accs[4] = {acc0, acc1, acc2, acc3};
#pragma unroll
    for (int w = 0; w < 4; ++w)
#pragma unroll
        for (int d4 = 0; d4 < 4; ++d4) {
            int cv = (int)((accs[w] >> (16 * d4)) & 0xFFFFULL);
            obase[(size_t)(w * 4 + d4) * Nn] = (cv >= 2) ? 1.f : 0.f;
        }
}

// ---------------- host orchestration ----------------
extern "C" void kernel_launch(void* const* d_in, const int* in_sizes, int n_in,
                              void* d_out, int out_size)
{
    const float* x     = (const float*)d_in[0];
    const float* y     = (const float*)d_in[1];
    const float* av_w  = (const float*)d_in[2];
    const float* av_g  = (const float*)d_in[3];
    const float* av_b  = (const float*)d_in[4];
    const float* va_w  = (const float*)d_in[5];
    const float* va_g  = (const float*)d_in[6];
    const float* va_b  = (const float*)d_in[7];
    const float* P_rpb = (const float*)d_in[8];
    const float* fc1_w = (const float*)d_in[9];
    const float* fc1_b = (const float*)d_in[10];
    const float* fc2_w = (const float*)d_in[11];
    const float* fc2_b = (const float*)d_in[12];
    const float* m1_w  = (const float*)d_in[13];
    const float* m1_b  = (const float*)d_in[14];
    const float* m1_g  = (const float*)d_in[15];
    const float* m1_bb = (const float*)d_in[16];
    const float* m2_w  = (const float*)d_in[17];
    const float* m2_b  = (const float*)d_in[18];
    const float* m2_g  = (const float*)d_in[19];
    const float* m2_bb = (const float*)d_in[20];
    float* out = (float*)d_out;

    float *zb, *hb, *sb, *x1b, *y1b, *curb;
    unsigned int *qmb, *kmb, *vmb;
    cudaGetSymbolAddress((void**)&zb,  g_z);
    cudaGetSymbolAddress((void**)&hb,  g_h);
    cudaGetSymbolAddress((void**)&sb,  g_s);
    cudaGetSymbolAddress((void**)&x1b, g_x1);
    cudaGetSymbolAddress((void**)&y1b, g_y1);
    cudaGetSymbolAddress((void**)&curb, g_cur);
    cudaGetSymbolAddress((void**)&qmb, g_qm);
    cudaGetSymbolAddress((void**)&kmb, g_km);
    cudaGetSymbolAddress((void**)&vmb, g_vm);

    const int nC  = TBm * Cc * Nn;     // 1,605,632
    const int nHD = TBm * HDd * Nn;    // 6,422,528

    auto gemm = [&](const float* A, const float* W, const float* bias,
                    float* o, int Cin, int Cout) {
        dim3 grid(98, Cout / 64);
        gemm_k<1, 0><<<grid, 128>>>(A, W, bias, nullptr, o, Cin, Cout, nullptr, nullptr);
    };

    auto sca = [&](const float* srcq, const float* srckv,
                   const float* W, const float* G, const float* Bt,
                   const float* rpb, const float* addbase, float* outbuf) {
        gemm(srcq, W, nullptr, zb, Cc, Cc);
        stats_k<<<Cc, 224>>>(zb, Cc);
        spike_mask_k<<<392, 256>>>(zb, G, Bt, qmb);

        gemm(srckv, W + Cc * Cc, nullptr, zb, Cc, Cc);
        stats_k<<<Cc, 224>>>(zb, Cc);
        spike_mask_k<<<392, 256>>>(zb, G + Cc, Bt + Cc, kmb);

        gemm(srckv, W + 2 * Cc * Cc, nullptr, zb, Cc, Cc);
        stats_k<<<Cc, 224>>>(zb, Cc);
        spike_mask_k<<<392, 256>>>(zb, G + 2 * Cc, Bt + 2 * Cc, vmb);

        attn_k<<<TBm * Hh, 224>>>(qmb, kmb, vmb, rpb, rpb != nullptr, sb);

        gemm(sb, W + 3 * Cc * Cc, nullptr, zb, Cc, Cc);
        stats_k<<<Cc, 224>>>(zb, Cc);
        spike_bn_k<<<nC / 256, 256>>>(zb, G + 3 * Cc, Bt + 3 * Cc, addbase, outbuf, Cc);
    };

    // x1 = x + sca(x, y, av);  y1 = y + sca(y, x, va, rpb)
    sca(x, y, av_w, av_g, av_b, nullptr, x, x1b);
    sca(y, x, va_w, va_g, va_b, P_rpb, y, y1b);

    // cur = LIF(fc1(x1) + fc2(y1))  — threshold fused into GEMM epilogue
    {
        dim3 grid(98, Cc / 64);
        gemm_k<2, 1><<<grid, 128>>>(x1b, fc1_w, fc1_b, fc2_b, curb, Cc, Cc, y1b, fc2_w);
    }

    // h = LIF(BN(m1(cur)))
    gemm(curb, m1_w, m1_b, zb, Cc, HDd);
    stats_k<<<HDd, 224>>>(zb, HDd);
    spike_bn_k<<<nHD / 256, 256>>>(zb, m1_g, m1_bb, nullptr, hb, HDd);

    // out = cur + LIF(BN(m2(h)))
    gemm(hb, m2_w, m2_b, zb, HDd, Cc);
    stats_k<<<Cc, 224>>>(zb, Cc);
    spike_bn_k<<<nC / 256, 256>>>(zb, m2_g, m2_bb, curb, out, Cc);

    (void)in_sizes; (void)n_in; (void)out_size;
}

// round 13
// speedup vs baseline: 1.8711x; 1.1525x over previous
#include <cuda_runtime.h>

// Problem constants
#define TBm 32       // T*B
#define Cc  256
#define Nn  196
#define Hh  16
#define Dd  16
#define HDd 1024
#define Jj  (TBm*Nn)        // 6272
#define NC  (TBm*Cc*Nn)     // 1,605,632
#define NHD (TBm*HDd*Nn)    // 6,422,528
#define MASKN (TBm*Hh*Nn)   // 100,352
#define EPSV 1e-5f

// ---------------- scratch (static device globals; no runtime alloc) -------------
__device__ float g_z [6*NC];         // 6 qkv buffers; also >= NHD for m1 scratch
__device__ float g_h [NHD];          // h spikes (m1 output)
__device__ float g_s [2*NC];         // attention o spikes (both sca branches)
__device__ float g_x1[NC];
__device__ float g_y1[NC];
__device__ float g_cur[NC];
__device__ unsigned int g_mask[6*MASKN];
__device__ float g_mu[6*Cc >= HDd ? 6*Cc : HDd];
__device__ float g_rs[6*Cc >= HDd ? 6*Cc : HDd];

// ---------------- GEMM core: out[m,d,n] = sum_c W[d,c]*A[m,c,n] ----------------
// Exact fp32, strictly ascending-k single-accumulator FMA per output element.
// Tile 64(d) x 64(j), BK=16, 128 threads, 8x4 per thread; register prefetch.
// NPASS=2: second pair (A2,W2), separate accumulators (pass0 fully, then pass1).
// MODE=0: store raw (+bias [+bias2]); MODE=1: store (v>=1)?1:0 (fused cur LIF).
template <int NPASS, int MODE>
__device__ __forceinline__ void gemm_body(
    const float* __restrict__ A, const float* __restrict__ W,
    const float* __restrict__ bias, const float* __restrict__ bias2,
    float* __restrict__ out, int Cin, int Cout,
    const float* __restrict__ A2, const float* __restrict__ W2)
{
    __shared__ float As[16][68];
    __shared__ float Bs[16][68];
    const int t  = threadIdx.x;
    const int d0 = blockIdx.y * 64;
    const int j0 = blockIdx.x * 64;
    const int tx = t & 15;           // j group: j = j0 + tx*4 .. +3
    const int ty = t >> 4;           // d group: d = d0 + ty*8 .. +7
    const int jj = t & 63;
    const int kr = t >> 6;           // 0..1  (k rows kr + 2*r, r<8)
    const int jB = j0 + jj;
    const int mB = jB / Nn;
    const int nB = jB - mB * Nn;
    const int kc = t & 15;           // k column
    const int dr = t >> 4;           // 0..7  (d rows dr + 8*r, r<8)

    float acc[NPASS][8][4];
#pragma unroll
    for (int p = 0; p < NPASS; p++)
#pragma unroll
        for (int i = 0; i < 8; i++)
#pragma unroll
            for (int q = 0; q < 4; q++) acc[p][i][q] = 0.f;

    float wreg[8], breg[8];

#pragma unroll 1
    for (int pass = 0; pass < NPASS; ++pass) {
        const float* Ain = pass ? A2 : A;
        const float* Win = pass ? W2 : W;
        const float* aptr = Ain + (size_t)mB * Cin * Nn + nB;
        const int nst = Cin >> 4;

        // prefetch stage 0
#pragma unroll
        for (int r = 0; r < 8; ++r)
            wreg[r] = Win[(size_t)(d0 + dr + 8*r) * Cin + kc];
#pragma unroll
        for (int r = 0; r < 8; ++r)
            breg[r] = aptr[(size_t)(kr + 2*r) * Nn];

#pragma unroll 1
        for (int s = 0; s < nst; ++s) {
            __syncthreads();
#pragma unroll
            for (int r = 0; r < 8; ++r) As[kc][dr + 8*r] = wreg[r];
#pragma unroll
            for (int r = 0; r < 8; ++r) Bs[kr + 2*r][jj] = breg[r];
            __syncthreads();

            if (s + 1 < nst) {
                const int c0 = (s + 1) << 4;
#pragma unroll
                for (int r = 0; r < 8; ++r)
                    wreg[r] = Win[(size_t)(d0 + dr + 8*r) * Cin + c0 + kc];
#pragma unroll
                for (int r = 0; r < 8; ++r)
                    breg[r] = aptr[(size_t)(c0 + kr + 2*r) * Nn];
            }
#pragma unroll
            for (int k = 0; k < 16; ++k) {
                float4 a0 = *reinterpret_cast<const float4*>(&As[k][ty * 8]);
                float4 a1 = *reinterpret_cast<const float4*>(&As[k][ty * 8 + 4]);
                float4 b4 = *reinterpret_cast<const float4*>(&Bs[k][tx * 4]);
                float a[8] = {a0.x, a0.y, a0.z, a0.w, a1.x, a1.y, a1.z, a1.w};
                float b[4] = {b4.x, b4.y, b4.z, b4.w};
#pragma unroll
                for (int i = 0; i < 8; i++)
#pragma unroll
                    for (int q = 0; q < 4; q++)
                        acc[pass][i][q] = __fmaf_rn(a[i], b[q], acc[pass][i][q]);
            }
        }
    }
#pragma unroll
    for (int q = 0; q < 4; q++) {
        int jw = j0 + tx * 4 + q;
        int mo = jw / Nn;
        int no = jw - mo * Nn;
        float* obase = out + (size_t)mo * Cout * Nn + no;
#pragma unroll
        for (int i = 0; i < 8; i++) {
            int dd = d0 + ty * 8 + i;
            float v = acc[0][i][q];
            if (bias)  v = __fadd_rn(v, bias[dd]);
            if (NPASS == 2) {
                float v2 = acc[1][i][q];
                if (bias2) v2 = __fadd_rn(v2, bias2[dd]);
                v = __fadd_rn(v, v2);
            }
            if (MODE == 1) v = (v >= 1.f) ? 1.f : 0.f;
            obase[(size_t)dd * Nn] = v;
        }
    }
}

template <int NPASS, int MODE>
__global__ __launch_bounds__(128) void gemm_k(
    const float* __restrict__ A, const float* __restrict__ W,
    const float* __restrict__ bias, const float* __restrict__ bias2,
    float* __restrict__ out, int Cin, int Cout,
    const float* __restrict__ A2, const float* __restrict__ W2)
{
    gemm_body<NPASS, MODE>(A, W, bias, bias2, out, Cin, Cout, A2, W2);
}

// Batched q/k/v GEMMs for BOTH sca branches (independent): z=0..5.
// z0: q_av(x), z1: k_av(y), z2: v_av(y), z3: q_va(y), z4: k_va(x), z5: v_va(x).
__global__ __launch_bounds__(128) void gemm6_k(
    const float* __restrict__ x, const float* __restrict__ y,
    const float* __restrict__ av_w, const float* __restrict__ va_w)
{
    const int z = blockIdx.z;
    const float* A = (z == 0 || z == 4 || z == 5) ? x : y;
    const float* W = (z < 3) ? av_w + (size_t)z * Cc * Cc
                             : va_w + (size_t)(z - 3) * Cc * Cc;
    gemm_body<1, 0>(A, W, nullptr, nullptr, g_z + (size_t)z * NC, Cc, Cc,
                    nullptr, nullptr);
}

// Batched projection GEMMs: z=0 (av, input s0), z=1 (va, input s1).
__global__ __launch_bounds__(128) void proj2_k(
    const float* __restrict__ av_w, const float* __restrict__ va_w)
{
    const int z = blockIdx.z;
    const float* A = g_s + (size_t)z * NC;
    const float* W = (z ? va_w : av_w) + (size_t)3 * Cc * Cc;
    gemm_body<1, 0>(A, W, nullptr, nullptr, g_z + (size_t)z * NC, Cc, Cc,
                    nullptr, nullptr);
}

// ---------------- XLA:GPU row-reduction replica (mean + var fused) ----------
// Bitwise-identical trees to the R6 passing version. Supports multiple
// contiguous buffers: channel cg = blockIdx.x, buf = cg/Cout, ch = cg%Cout.
__global__ __launch_bounds__(224) void stats_k(const float* __restrict__ zb, int Cout)
{
    const int cg = blockIdx.x;
    const int buf = cg / Cout;
    const int ch = cg - buf * Cout;
    const int t = threadIdx.x;
    __shared__ float sw[7];
    __shared__ float smu;
    const int lane = t & 31, w = t >> 5;
    const float* base = zb + (size_t)buf * TBm * Cout * Nn + (size_t)ch * Nn + t;

    // ---- mean ----
    float p = 0.f;
    if (t < Nn)
        for (int m = 0; m < TBm; ++m)
            p = __fadd_rn(p, base[(size_t)m * Cout * Nn]);
#pragma unroll
    for (int off = 16; off; off >>= 1)
        p = __fadd_rn(p, __shfl_down_sync(0xFFFFFFFFu, p, off));
    if (!lane) sw[w] = p;
    __syncthreads();
    if (w == 0) {
        float v = (lane < 7) ? sw[lane] : 0.f;
#pragma unroll
        for (int off = 16; off; off >>= 1)
            v = __fadd_rn(v, __shfl_down_sync(0xFFFFFFFFu, v, off));
        if (!lane) { smu = __fdiv_rn(v, 6272.f); g_mu[cg] = smu; }
    }
    __syncthreads();
    const float mu = smu;

    // ---- var ----
    p = 0.f;
    if (t < Nn)
        for (int m = 0; m < TBm; ++m) {
            float dv = __fsub_rn(base[(size_t)m * Cout * Nn], mu);
            p = __fadd_rn(p, __fmul_rn(dv, dv));
        }
#pragma unroll
    for (int off = 16; off; off >>= 1)
        p = __fadd_rn(p, __shfl_down_sync(0xFFFFFFFFu, p, off));
    __syncthreads();
    if (!lane) sw[w] = p;
    __syncthreads();
    if (w == 0) {
        float v = (lane < 7) ? sw[lane] : 0.f;
#pragma unroll
        for (int off = 16; off; off >>= 1)
            v = __fadd_rn(v, __shfl_down_sync(0xFFFFFFFFu, v, off));
        if (!lane) {
            float var = __fdiv_rn(v, 6272.f);
            g_rs[cg] = rsqrtf(__fadd_rn(var, EPSV));
        }
    }
}

// BN affine exactly as reference: ((g*(z-mu))*rs)+b, separate roundings
__device__ __forceinline__ float bn_val(float v, float g, float mu, float rs, float b)
{
    return __fadd_rn(__fmul_rn(__fmul_rn(g, __fsub_rn(v, mu)), rs), b);
}

// ---------------- batched BN+LIF -> 16-bit head masks for all 6 branches -------
__global__ __launch_bounds__(256) void mask6_k(
    const float* __restrict__ av_g, const float* __restrict__ av_b,
    const float* __restrict__ va_g, const float* __restrict__ va_b)
{
    const int z = blockIdx.y;
    const float* G  = (z < 3) ? av_g + z * Cc : va_g + (z - 3) * Cc;
    const float* Bt = (z < 3) ? av_b + z * Cc : va_b + (z - 3) * Cc;
    const float* zbuf = g_z + (size_t)z * NC;
    const int muoff = z * Cc;
    int idx = blockIdx.x * 256 + threadIdx.x;     // MASKN threads
    int n  = idx % Nn;
    int th = idx / Nn;
    int h  = th & 15;
    int m  = th >> 4;
    const float* zb = zbuf + (size_t)m * Cc * Nn + (size_t)h * Dd * Nn + n;
    unsigned int msk = 0;
#pragma unroll
    for (int d = 0; d < Dd; ++d) {
        int c = h * Dd + d;
        float bn = bn_val(zb[(size_t)d * Nn], G[c], g_mu[muoff + c], g_rs[muoff + c], Bt[c]);
        if (bn >= 1.f) msk |= (1u << d);
    }
    g_mask[(size_t)z * MASKN + idx] = msk;
}

// ---------------- BN+LIF elementwise (single buffer; optional residual) --------
__global__ __launch_bounds__(256) void spike_bn_k(
    const float* __restrict__ z, const float* __restrict__ g,
    const float* __restrict__ b, const float* __restrict__ addsrc,
    float* __restrict__ out, int Cout)
{
    int idx = blockIdx.x * 256 + threadIdx.x;
    int c = (idx / Nn) % Cout;
    float bn = bn_val(z[idx], g[c], g_mu[c], g_rs[c], b[c]);
    float s = (bn >= 1.f) ? 1.f : 0.f;
    out[idx] = addsrc ? __fadd_rn(addsrc[idx], s) : s;
}

// ---------------- batched BN+LIF + residual for both proj branches -------------
__global__ __launch_bounds__(256) void bn2_k(
    const float* __restrict__ xin, const float* __restrict__ yin,
    const float* __restrict__ av_g, const float* __restrict__ av_b,
    const float* __restrict__ va_g, const float* __restrict__ va_b)
{
    const int z = blockIdx.y;
    const float* G  = (z ? va_g : av_g) + 3 * Cc;
    const float* Bt = (z ? va_b : av_b) + 3 * Cc;
    const float* addsrc = z ? yin : xin;
    float* outp = z ? g_y1 : g_x1;
    const float* zin = g_z + (size_t)z * NC;
    const int muoff = z * Cc;
    int idx = blockIdx.x * 256 + threadIdx.x;
    int c = (idx / Nn) % Cc;
    float bn = bn_val(zin[idx], G[c], g_mu[muoff + c], g_rs[muoff + c], Bt[c]);
    float s = (bn >= 1.f) ? 1.f : 0.f;
    outp[idx] = __fadd_rn(addsrc[idx], s);
}

// ---------------- attention (both branches batched): exact integer bit-packed ---
__global__ __launch_bounds__(224) void attn2_k(const float* __restrict__ P)
{
    const int z = blockIdx.y;             // 0: av (no rpb), 1: va (rpb)
    const int use_rpb = z;
    const unsigned int* qm = g_mask + (size_t)(3 * z + 0) * MASKN;
    const unsigned int* km = g_mask + (size_t)(3 * z + 1) * MASKN;
    const unsigned int* vm = g_mask + (size_t)(3 * z + 2) * MASKN;
    float* out = g_s + (size_t)z * NC;

    __shared__ unsigned int skm[Nn];
    __shared__ unsigned long long sv[Nn][4];
    __shared__ float sP[29 * 29];
    const int tbh = blockIdx.x;
    const int mb = tbh >> 4;
    const int h  = tbh & 15;
    const int base = tbh * Nn;
    const int t = threadIdx.x;
    for (int i = t; i < Nn; i += 224) {
        skm[i] = km[base + i];
        unsigned int v = vm[base + i];
#pragma unroll
        for (int w = 0; w < 4; ++w) {
            unsigned long long xL = 0;
#pragma unroll
            for (int d = 0; d < 4; ++d)
                xL |= (unsigned long long)((v >> (w * 4 + d)) & 1u) << (16 * d);
            sv[i][w] = xL;
        }
    }
    if (use_rpb)
        for (int i = t; i < 841; i += 224) sP[i] = P[i];
    __syncthreads();
    if (t >= Nn) return;

    const unsigned int q = qm[base + t];
    unsigned long long acc0 = 0, acc1 = 0, acc2 = 0, acc3 = 0;
    if (use_rpb) {
        const int ni = t / 14, nj = t - (t / 14) * 14;
        const float* prow = sP + (ni + 14) * 29 + (nj + 14);
        int m = 0;
        for (int ki = 0; ki < 14; ++ki) {
            const float* pr = prow - ki * 29;
#pragma unroll
            for (int kj = 0; kj < 14; ++kj, ++m) {
                int cnt = __popc(q & skm[m]);
                if (__fadd_rn((float)cnt, pr[-kj]) >= 1.f) {
                    acc0 += sv[m][0]; acc1 += sv[m][1];
                    acc2 += sv[m][2]; acc3 += sv[m][3];
                }
            }
        }
    } else {
#pragma unroll 4
        for (int m = 0; m < Nn; ++m) {
            unsigned long long c = (unsigned long long)__popc(q & skm[m]);
            acc0 += sv[m][0] * c; acc1 += sv[m][1] * c;
            acc2 += sv[m][2] * c; acc3 += sv[m][3] * c;
        }
    }
    float* obase = out + (size_t)mb * Cc * Nn + (size_t)h * Dd * Nn + t;
    unsigned long long accs[4] = {acc0, acc1, acc2, acc3};
#pragma unroll
    for (int w = 0; w < 4; ++w)
#pragma unroll
        for (int d4 = 0; d4 < 4; ++d4) {
            int cv = (int)((accs[w] >> (16 * d4)) & 0xFFFFULL);
            obase[(size_t)(w * 4 + d4) * Nn] = (cv >= 2) ? 1.f : 0.f;
        }
}

// ---------------- host orchestration ----------------
extern "C" void kernel_launch(void* const* d_in, const int* in_sizes, int n_in,
                              void* d_out, int out_size)
{
    const float* x     = (const float*)d_in[0];
    const float* y     = (const float*)d_in[1];
    const float* av_w  = (const float*)d_in[2];
    const float* av_g  = (const float*)d_in[3];
    const float* av_b  = (const float*)d_in[4];
    const float* va_w  = (const float*)d_in[5];
    const float* va_g  = (const float*)d_in[6];
    const float* va_b  = (const float*)d_in[7];
    const float* P_rpb = (const float*)d_in[8];
    const float* fc1_w = (const float*)d_in[9];
    const float* fc1_b = (const float*)d_in[10];
    const float* fc2_w = (const float*)d_in[11];
    const float* fc2_b = (const float*)d_in[12];
    const float* m1_w  = (const float*)d_in[13];
    const float* m1_b  = (const float*)d_in[14];
    const float* m1_g  = (const float*)d_in[15];
    const float* m1_bb = (const float*)d_in[16];
    const float* m2_w  = (const float*)d_in[17];
    const float* m2_b  = (const float*)d_in[18];
    const float* m2_g  = (const float*)d_in[19];
    const float* m2_bb = (const float*)d_in[20];
    float* out = (float*)d_out;

    float *zb, *hb, *x1b, *y1b, *curb;
    cudaGetSymbolAddress((void**)&zb,  g_z);
    cudaGetSymbolAddress((void**)&hb,  g_h);
    cudaGetSymbolAddress((void**)&x1b, g_x1);
    cudaGetSymbolAddress((void**)&y1b, g_y1);
    cudaGetSymbolAddress((void**)&curb, g_cur);

    // ---- phase 1: all six q/k/v convs (both sca branches), batched ----
    gemm6_k<<<dim3(98, 4, 6), 128>>>(x, y, av_w, va_w);
    stats_k<<<6 * Cc, 224>>>(zb, Cc);
    mask6_k<<<dim3(392, 6), 256>>>(av_g, av_b, va_g, va_b);

    // ---- phase 2: both attentions, batched ----
    attn2_k<<<dim3(TBm * Hh, 2), 224>>>(P_rpb);

    // ---- phase 3: both projection convs + BN + LIF + residual ----
    proj2_k<<<dim3(98, 4, 2), 128>>>(av_w, va_w);
    stats_k<<<2 * Cc, 224>>>(zb, Cc);
    bn2_k<<<dim3(NC / 256, 2), 256>>>(x, y, av_g, av_b, va_g, va_b);

    // ---- cur = LIF(fc1(x1) + fc2(y1)) : threshold fused into GEMM epilogue ----
    gemm_k<2, 1><<<dim3(98, 4), 128>>>(x1b, fc1_w, fc1_b, fc2_b, curb, Cc, Cc,
                                       y1b, fc2_w);

    // ---- h = LIF(BN(m1(cur))) ----
    gemm_k<1, 0><<<dim3(98, 16), 128>>>(curb, m1_w, m1_b, nullptr, zb, Cc, HDd,
                                        nullptr, nullptr);
    stats_k<<<HDd, 224>>>(zb, HDd);
    spike_bn_k<<<NHD / 256, 256>>>(zb, m1_g, m1_bb, nullptr, hb, HDd);

    // ---- out = cur + LIF(BN(m2(h))) ----
    gemm_k<1, 0><<<dim3(98, 4), 128>>>(hb, m2_w, m2_b, nullptr, zb, HDd, Cc,
                                       nullptr, nullptr);
    stats_k<<<Cc, 224>>>(zb, Cc);
    spike_bn_k<<<NC / 256, 256>>>(zb, m2_g, m2_bb, curb, out, Cc);

    (void)in_sizes; (void)n_in; (void)out_size;
}

// round 14
// speedup vs baseline: 1.9397x; 1.0367x over previous
#include <cuda_runtime.h>

// Problem constants
#define TBm 32       // T*B
#define Cc  256
#define Nn  196
#define Hh  16
#define Dd  16
#define HDd 1024
#define Jj  (TBm*Nn)        // 6272
#define NC  (TBm*Cc*Nn)     // 1,605,632
#define NHD (TBm*HDd*Nn)    // 6,422,528
#define MASKN (TBm*Hh*Nn)   // 100,352
#define EPSV 1e-5f

// ---------------- scratch (static device globals; no runtime alloc) -------------
__device__ float g_z [6*NC];         // 6 qkv buffers; also >= NHD for m1 scratch
__device__ float g_h [NHD];          // h spikes (m1 output)
__device__ float g_s [2*NC];         // attention o spikes (both sca branches)
__device__ float g_x1[NC];
__device__ float g_y1[NC];
__device__ float g_cur[NC];
__device__ unsigned int g_mask[6*MASKN];
__device__ float g_mu[6*Cc >= HDd ? 6*Cc : HDd];
__device__ float g_rs[6*Cc >= HDd ? 6*Cc : HDd];

// ---------------- GEMM core: out[m,d,n] = sum_c W[d,c]*A[m,c,n] ----------------
// Exact fp32, strictly ascending-k single-accumulator FMA per output element.
// Tile 64(d) x 64(j), BK=16, 128 threads, 8x4 per thread; register prefetch.
// MODE=0: store raw (+bias).
__device__ __forceinline__ void gemm_body(
    const float* __restrict__ A, const float* __restrict__ W,
    const float* __restrict__ bias,
    float* __restrict__ out, int Cin, int Cout)
{
    __shared__ float As[16][68];
    __shared__ float Bs[16][68];
    const int t  = threadIdx.x;
    const int d0 = blockIdx.y * 64;
    const int j0 = blockIdx.x * 64;
    const int tx = t & 15;           // j group: j = j0 + tx*4 .. +3
    const int ty = t >> 4;           // d group: d = d0 + ty*8 .. +7
    const int jj = t & 63;
    const int kr = t >> 6;           // 0..1  (k rows kr + 2*r, r<8)
    const int jB = j0 + jj;
    const int mB = jB / Nn;
    const int nB = jB - mB * Nn;
    const int kc = t & 15;           // k column
    const int dr = t >> 4;           // 0..7  (d rows dr + 8*r, r<8)

    float acc[8][4];
#pragma unroll
    for (int i = 0; i < 8; i++)
#pragma unroll
        for (int q = 0; q < 4; q++) acc[i][q] = 0.f;

    float wreg[8], breg[8];
    const float* aptr = A + (size_t)mB * Cin * Nn + nB;
    const int nst = Cin >> 4;

    // prefetch stage 0
#pragma unroll
    for (int r = 0; r < 8; ++r)
        wreg[r] = W[(size_t)(d0 + dr + 8*r) * Cin + kc];
#pragma unroll
    for (int r = 0; r < 8; ++r)
        breg[r] = aptr[(size_t)(kr + 2*r) * Nn];

#pragma unroll 1
    for (int s = 0; s < nst; ++s) {
        __syncthreads();
#pragma unroll
        for (int r = 0; r < 8; ++r) As[kc][dr + 8*r] = wreg[r];
#pragma unroll
        for (int r = 0; r < 8; ++r) Bs[kr + 2*r][jj] = breg[r];
        __syncthreads();

        if (s + 1 < nst) {
            const int c0 = (s + 1) << 4;
#pragma unroll
            for (int r = 0; r < 8; ++r)
                wreg[r] = W[(size_t)(d0 + dr + 8*r) * Cin + c0 + kc];
#pragma unroll
            for (int r = 0; r < 8; ++r)
                breg[r] = aptr[(size_t)(c0 + kr + 2*r) * Nn];
        }
#pragma unroll
        for (int k = 0; k < 16; ++k) {
            float4 a0 = *reinterpret_cast<const float4*>(&As[k][ty * 8]);
            float4 a1 = *reinterpret_cast<const float4*>(&As[k][ty * 8 + 4]);
            float4 b4 = *reinterpret_cast<const float4*>(&Bs[k][tx * 4]);
            float a[8] = {a0.x, a0.y, a0.z, a0.w, a1.x, a1.y, a1.z, a1.w};
            float b[4] = {b4.x, b4.y, b4.z, b4.w};
#pragma unroll
            for (int i = 0; i < 8; i++)
#pragma unroll
                for (int q = 0; q < 4; q++)
                    acc[i][q] = __fmaf_rn(a[i], b[q], acc[i][q]);
        }
    }
#pragma unroll
    for (int q = 0; q < 4; q++) {
        int jw = j0 + tx * 4 + q;
        int mo = jw / Nn;
        int no = jw - mo * Nn;
        float* obase = out + (size_t)mo * Cout * Nn + no;
#pragma unroll
        for (int i = 0; i < 8; i++) {
            int dd = d0 + ty * 8 + i;
            float v = acc[i][q];
            if (bias) v = __fadd_rn(v, bias[dd]);
            obase[(size_t)dd * Nn] = v;
        }
    }
}

__global__ __launch_bounds__(128) void gemm_k(
    const float* __restrict__ A, const float* __restrict__ W,
    const float* __restrict__ bias, float* __restrict__ out, int Cin, int Cout)
{
    gemm_body(A, W, bias, out, Cin, Cout);
}

// Batched q/k/v GEMMs for BOTH sca branches (independent): z=0..5.
// z0: q_av(x), z1: k_av(y), z2: v_av(y), z3: q_va(y), z4: k_va(x), z5: v_va(x).
__global__ __launch_bounds__(128) void gemm6_k(
    const float* __restrict__ x, const float* __restrict__ y,
    const float* __restrict__ av_w, const float* __restrict__ va_w)
{
    const int z = blockIdx.z;
    const float* A = (z == 0 || z == 4 || z == 5) ? x : y;
    const float* W = (z < 3) ? av_w + (size_t)z * Cc * Cc
                             : va_w + (size_t)(z - 3) * Cc * Cc;
    gemm_body(A, W, nullptr, g_z + (size_t)z * NC, Cc, Cc);
}

// Batched projection GEMMs: z=0 (av, input s0), z=1 (va, input s1).
__global__ __launch_bounds__(128) void proj2_k(
    const float* __restrict__ av_w, const float* __restrict__ va_w)
{
    const int z = blockIdx.z;
    gemm_body(g_s + (size_t)z * NC, (z ? va_w : av_w) + (size_t)3 * Cc * Cc,
              nullptr, g_z + (size_t)z * NC, Cc, Cc);
}

// Batched fc GEMMs: z=0 fc1(x1), z=1 fc2(y1) -> g_z[z].
__global__ __launch_bounds__(128) void fc2g_k(
    const float* __restrict__ fc1_w, const float* __restrict__ fc1_b,
    const float* __restrict__ fc2_w, const float* __restrict__ fc2_b)
{
    const int z = blockIdx.z;
    gemm_body(z ? g_y1 : g_x1, z ? fc2_w : fc1_w, z ? fc2_b : fc1_b,
              g_z + (size_t)z * NC, Cc, Cc);
}

// cur = LIF(zx + zy): identical rounding to reference ((acc+b1)+(acc2+b2)).
__global__ __launch_bounds__(256) void cur_k()
{
    int idx = blockIdx.x * 256 + threadIdx.x;
    float v = __fadd_rn(g_z[idx], g_z[(size_t)NC + idx]);
    g_cur[idx] = (v >= 1.f) ? 1.f : 0.f;
}

// ---------------- XLA:GPU row-reduction replica (mean + var fused) ----------
// Bitwise-identical trees to the R6 passing version. Supports multiple
// contiguous buffers: channel cg = blockIdx.x, buf = cg/Cout, ch = cg%Cout.
__global__ __launch_bounds__(224) void stats_k(const float* __restrict__ zb, int Cout)
{
    const int cg = blockIdx.x;
    const int buf = cg / Cout;
    const int ch = cg - buf * Cout;
    const int t = threadIdx.x;
    __shared__ float sw[7];
    __shared__ float smu;
    const int lane = t & 31, w = t >> 5;
    const float* base = zb + (size_t)buf * TBm * Cout * Nn + (size_t)ch * Nn + t;

    // ---- mean ----
    float p = 0.f;
    if (t < Nn)
        for (int m = 0; m < TBm; ++m)
            p = __fadd_rn(p, base[(size_t)m * Cout * Nn]);
#pragma unroll
    for (int off = 16; off; off >>= 1)
        p = __fadd_rn(p, __shfl_down_sync(0xFFFFFFFFu, p, off));
    if (!lane) sw[w] = p;
    __syncthreads();
    if (w == 0) {
        float v = (lane < 7) ? sw[lane] : 0.f;
#pragma unroll
        for (int off = 16; off; off >>= 1)
            v = __fadd_rn(v, __shfl_down_sync(0xFFFFFFFFu, v, off));
        if (!lane) { smu = __fdiv_rn(v, 6272.f); g_mu[cg] = smu; }
    }
    __syncthreads();
    const float mu = smu;

    // ---- var ----
    p = 0.f;
    if (t < Nn)
        for (int m = 0; m < TBm; ++m) {
            float dv = __fsub_rn(base[(size_t)m * Cout * Nn], mu);
            p = __fadd_rn(p, __fmul_rn(dv, dv));
        }
#pragma unroll
    for (int off = 16; off; off >>= 1)
        p = __fadd_rn(p, __shfl_down_sync(0xFFFFFFFFu, p, off));
    __syncthreads();
    if (!lane) sw[w] = p;
    __syncthreads();
    if (w == 0) {
        float v = (lane < 7) ? sw[lane] : 0.f;
#pragma unroll
        for (int off = 16; off; off >>= 1)
            v = __fadd_rn(v, __shfl_down_sync(0xFFFFFFFFu, v, off));
        if (!lane) {
            float var = __fdiv_rn(v, 6272.f);
            g_rs[cg] = rsqrtf(__fadd_rn(var, EPSV));
        }
    }
}

// BN affine exactly as reference: ((g*(z-mu))*rs)+b, separate roundings
__device__ __forceinline__ float bn_val(float v, float g, float mu, float rs, float b)
{
    return __fadd_rn(__fmul_rn(__fmul_rn(g, __fsub_rn(v, mu)), rs), b);
}

// ---------------- batched BN+LIF -> 16-bit head masks for all 6 branches -------
__global__ __launch_bounds__(256) void mask6_k(
    const float* __restrict__ av_g, const float* __restrict__ av_b,
    const float* __restrict__ va_g, const float* __restrict__ va_b)
{
    const int z = blockIdx.y;
    const float* G  = (z < 3) ? av_g + z * Cc : va_g + (z - 3) * Cc;
    const float* Bt = (z < 3) ? av_b + z * Cc : va_b + (z - 3) * Cc;
    const float* zbuf = g_z + (size_t)z * NC;
    const int muoff = z * Cc;
    int idx = blockIdx.x * 256 + threadIdx.x;     // MASKN threads
    int n  = idx % Nn;
    int th = idx / Nn;
    int h  = th & 15;
    int m  = th >> 4;
    const float* zb = zbuf + (size_t)m * Cc * Nn + (size_t)h * Dd * Nn + n;
    unsigned int msk = 0;
#pragma unroll
    for (int d = 0; d < Dd; ++d) {
        int c = h * Dd + d;
        float bn = bn_val(zb[(size_t)d * Nn], G[c], g_mu[muoff + c], g_rs[muoff + c], Bt[c]);
        if (bn >= 1.f) msk |= (1u << d);
    }
    g_mask[(size_t)z * MASKN + idx] = msk;
}

// ---------------- BN+LIF elementwise (single buffer; optional residual) --------
__global__ __launch_bounds__(256) void spike_bn_k(
    const float* __restrict__ z, const float* __restrict__ g,
    const float* __restrict__ b, const float* __restrict__ addsrc,
    float* __restrict__ out, int Cout)
{
    int idx = blockIdx.x * 256 + threadIdx.x;
    int c = (idx / Nn) % Cout;
    float bn = bn_val(z[idx], g[c], g_mu[c], g_rs[c], b[c]);
    float s = (bn >= 1.f) ? 1.f : 0.f;
    out[idx] = addsrc ? __fadd_rn(addsrc[idx], s) : s;
}

// ---------------- batched BN+LIF + residual for both proj branches -------------
__global__ __launch_bounds__(256) void bn2_k(
    const float* __restrict__ xin, const float* __restrict__ yin,
    const float* __restrict__ av_g, const float* __restrict__ av_b,
    const float* __restrict__ va_g, const float* __restrict__ va_b)
{
    const int z = blockIdx.y;
    const float* G  = (z ? va_g : av_g) + 3 * Cc;
    const float* Bt = (z ? va_b : av_b) + 3 * Cc;
    const float* addsrc = z ? yin : xin;
    float* outp = z ? g_y1 : g_x1;
    const float* zin = g_z + (size_t)z * NC;
    const int muoff = z * Cc;
    int idx = blockIdx.x * 256 + threadIdx.x;
    int c = (idx / Nn) % Cc;
    float bn = bn_val(zin[idx], G[c], g_mu[muoff + c], g_rs[muoff + c], Bt[c]);
    float s = (bn >= 1.f) ? 1.f : 0.f;
    outp[idx] = __fadd_rn(addsrc[idx], s);
}

// ---------------- attention (both branches batched): exact integer, u32 lanes ---
// acc[w] (w=0..7) holds counts for d=2w (lo16) and d=2w+1 (hi16); max 3136.
__global__ __launch_bounds__(224) void attn2_k(const float* __restrict__ P)
{
    const int z = blockIdx.y;             // 0: av (no rpb), 1: va (rpb)
    const unsigned int* qm = g_mask + (size_t)(3 * z + 0) * MASKN;
    const unsigned int* km = g_mask + (size_t)(3 * z + 1) * MASKN;
    const unsigned int* vm = g_mask + (size_t)(3 * z + 2) * MASKN;
    float* out = g_s + (size_t)z * NC;

    __shared__ unsigned int skm[Nn];
    __shared__ unsigned int sv[Nn][8];
    __shared__ float sP[29 * 29];
    const int tbh = blockIdx.x;
    const int mb = tbh >> 4;
    const int h  = tbh & 15;
    const int base = tbh * Nn;
    const int t = threadIdx.x;
    for (int i = t; i < Nn; i += 224) {
        skm[i] = km[base + i];
        unsigned int v = vm[base + i];
#pragma unroll
        for (int w = 0; w < 8; ++w)
            sv[i][w] = ((v >> (2*w)) & 1u) | (((v >> (2*w + 1)) & 1u) << 16);
    }
    if (z)
        for (int i = t; i < 841; i += 224) sP[i] = P[i];
    __syncthreads();
    if (t >= Nn) return;

    const unsigned int q = qm[base + t];
    unsigned int acc[8] = {0, 0, 0, 0, 0, 0, 0, 0};
    if (z) {
        const int ni = t / 14, nj = t - (t / 14) * 14;
        const float* prow = sP + (ni + 14) * 29 + (nj + 14);
        int m = 0;
        for (int ki = 0; ki < 14; ++ki) {
            const float* pr = prow - ki * 29;
#pragma unroll 2
            for (int kj = 0; kj < 14; ++kj, ++m) {
                int cnt = __popc(q & skm[m]);
                unsigned int msk =
                    (__fadd_rn((float)cnt, pr[-kj]) >= 1.f) ? 0xFFFFFFFFu : 0u;
#pragma unroll
                for (int w = 0; w < 8; ++w) acc[w] += sv[m][w] & msk;
            }
        }
    } else {
#pragma unroll 4
        for (int m = 0; m < Nn; ++m) {
            unsigned int c = (unsigned int)__popc(q & skm[m]);
#pragma unroll
            for (int w = 0; w < 8; ++w) acc[w] += c * sv[m][w];
        }
    }
    float* obase = out + (size_t)mb * Cc * Nn + (size_t)h * Dd * Nn + t;
#pragma unroll
    for (int w = 0; w < 8; ++w) {
        int lo = (int)(acc[w] & 0xFFFFu);
        int hi = (int)(acc[w] >> 16);
        obase[(size_t)(2*w)     * Nn] = (lo >= 2) ? 1.f : 0.f;  // o*0.25>=0.5
        obase[(size_t)(2*w + 1) * Nn] = (hi >= 2) ? 1.f : 0.f;
    }
}

// ---------------- host orchestration ----------------
extern "C" void kernel_launch(void* const* d_in, const int* in_sizes, int n_in,
                              void* d_out, int out_size)
{
    const float* x     = (const float*)d_in[0];
    const float* y     = (const float*)d_in[1];
    const float* av_w  = (const float*)d_in[2];
    const float* av_g  = (const float*)d_in[3];
    const float* av_b  = (const float*)d_in[4];
    const float* va_w  = (const float*)d_in[5];
    const float* va_g  = (const float*)d_in[6];
    const float* va_b  = (const float*)d_in[7];
    const float* P_rpb = (const float*)d_in[8];
    const float* fc1_w = (const float*)d_in[9];
    const float* fc1_b = (const float*)d_in[10];
    const float* fc2_w = (const float*)d_in[11];
    const float* fc2_b = (const float*)d_in[12];
    const float* m1_w  = (const float*)d_in[13];
    const float* m1_b  = (const float*)d_in[14];
    const float* m1_g  = (const float*)d_in[15];
    const float* m1_bb = (const float*)d_in[16];
    const float* m2_w  = (const float*)d_in[17];
    const float* m2_b  = (const float*)d_in[18];
    const float* m2_g  = (const float*)d_in[19];
    const float* m2_bb = (const float*)d_in[20];
    float* out = (float*)d_out;

    float *zb, *hb, *curb;
    cudaGetSymbolAddress((void**)&zb,  g_z);
    cudaGetSymbolAddress((void**)&hb,  g_h);
    cudaGetSymbolAddress((void**)&curb, g_cur);

    // ---- phase 1: all six q/k/v convs (both sca branches), batched ----
    gemm6_k<<<dim3(98, 4, 6), 128>>>(x, y, av_w, va_w);
    stats_k<<<6 * Cc, 224>>>(zb, Cc);
    mask6_k<<<dim3(392, 6), 256>>>(av_g, av_b, va_g, va_b);

    // ---- phase 2: both attentions, batched ----
    attn2_k<<<dim3(TBm * Hh, 2), 224>>>(P_rpb);

    // ---- phase 3: both projection convs + BN + LIF + residual ----
    proj2_k<<<dim3(98, 4, 2), 128>>>(av_w, va_w);
    stats_k<<<2 * Cc, 224>>>(zb, Cc);
    bn2_k<<<dim3(NC / 256, 2), 256>>>(x, y, av_g, av_b, va_g, va_b);

    // ---- cur = LIF(fc1(x1) + fc2(y1)) : batched GEMMs + fused add/LIF ----
    fc2g_k<<<dim3(98, 4, 2), 128>>>(fc1_w, fc1_b, fc2_w, fc2_b);
    cur_k<<<NC / 256, 256>>>();

    // ---- h = LIF(BN(m1(cur))) ----
    gemm_k<<<dim3(98, 16), 128>>>(curb, m1_w, m1_b, zb, Cc, HDd);
    stats_k<<<HDd, 224>>>(zb, HDd);
    spike_bn_k<<<NHD / 256, 256>>>(zb, m1_g, m1_bb, nullptr, hb, HDd);

    // ---- out = cur + LIF(BN(m2(h))) ----
    gemm_k<<<dim3(98, 4), 128>>>(hb, m2_w, m2_b, zb, HDd, Cc);
    stats_k<<<Cc, 224>>>(zb, Cc);
    spike_bn_k<<<NC / 256, 256>>>(zb, m2_g, m2_bb, curb, out, Cc);

    (void)in_sizes; (void)n_in; (void)out_size;
}